// round 3
// baseline (speedup 1.0000x reference)
#include <cuda_runtime.h>
#include <math.h>

#define S_  2048
#define B_  4
#define D_  1024
#define H_  16
#define DH_ 64
#define F_  4096
#define M_  8192   // S_*B_

// ---------------- scratch (device globals; no allocation allowed) ------------
__device__ float g_h  [M_ * D_];
__device__ float g_q  [M_ * D_];
__device__ float g_k  [M_ * D_];
__device__ float g_v  [M_ * D_];
__device__ float g_ctx[M_ * D_];
__device__ float g_x1 [M_ * D_];
__device__ float g_h2 [M_ * D_];
__device__ float g_ff [(size_t)M_ * F_];

// ---------------- block reduction -------------------------------------------
__device__ __forceinline__ float blockReduceSum256(float val) {
    __shared__ float sh[8];
    #pragma unroll
    for (int o = 16; o; o >>= 1) val += __shfl_xor_sync(0xffffffffu, val, o);
    int w = threadIdx.x >> 5;
    if ((threadIdx.x & 31) == 0) sh[w] = val;
    __syncthreads();
    float tot = 0.f;
    #pragma unroll
    for (int i = 0; i < 8; i++) tot += sh[i];
    __syncthreads();   // protect sh for a subsequent call
    return tot;
}

// ---------------- LayerNorm: one block per row (D=1024, 256 thr) -------------
__global__ void ln_kernel(const float* __restrict__ x,
                          const float* __restrict__ g,
                          const float* __restrict__ b,
                          float* __restrict__ out) {
    int row = blockIdx.x;
    const float4* xr = (const float4*)(x + (size_t)row * D_);
    float4 xv = xr[threadIdx.x];

    float s = xv.x + xv.y + xv.z + xv.w;
    float mean = blockReduceSum256(s) * (1.0f / D_);

    float dx0 = xv.x - mean, dx1 = xv.y - mean, dx2 = xv.z - mean, dx3 = xv.w - mean;
    float s2 = dx0*dx0 + dx1*dx1 + dx2*dx2 + dx3*dx3;
    float var = blockReduceSum256(s2) * (1.0f / D_);
    float inv = rsqrtf(var + 1e-5f);

    float4 gv = ((const float4*)g)[threadIdx.x];
    float4 bv = ((const float4*)b)[threadIdx.x];
    float4 o;
    o.x = dx0 * inv * gv.x + bv.x;
    o.y = dx1 * inv * gv.y + bv.y;
    o.z = dx2 * inv * gv.z + bv.z;
    o.w = dx3 * inv * gv.w + bv.w;
    ((float4*)(out + (size_t)row * D_))[threadIdx.x] = o;
}

// ---------------- SGEMM 128x128x8, 8x8 per thread, fused epilogue ------------
// EPI: 0 = +bias, 1 = +bias then relu, 2 = +bias +residual
template<int EPI>
__global__ void __launch_bounds__(256, 2)
gemm_kernel(const float* __restrict__ A, const float* __restrict__ Bm,
            const float* __restrict__ bias, const float* __restrict__ res,
            float* __restrict__ C, int M, int N, int K) {
    __shared__ float As[8][128];
    __shared__ float Bs[8][128];

    const int tid = threadIdx.x;
    const int tx = tid & 15, ty = tid >> 4;
    const int m0 = blockIdx.y * 128, n0 = blockIdx.x * 128;

    float c[8][8];
    #pragma unroll
    for (int i = 0; i < 8; i++)
        #pragma unroll
        for (int j = 0; j < 8; j++) c[i][j] = 0.f;

    const int aRow = tid >> 1, aCol = (tid & 1) << 2;
    const int bRow = tid >> 5, bCol = (tid & 31) << 2;
    const float* Aptr = A + (size_t)(m0 + aRow) * K + aCol;
    const float* Bptr = Bm + (size_t)bRow * N + n0 + bCol;

    for (int k0 = 0; k0 < K; k0 += 8) {
        float4 a4 = *(const float4*)(Aptr + k0);
        float4 b4 = *(const float4*)(Bptr + (size_t)k0 * N);
        As[aCol + 0][aRow] = a4.x;
        As[aCol + 1][aRow] = a4.y;
        As[aCol + 2][aRow] = a4.z;
        As[aCol + 3][aRow] = a4.w;
        *(float4*)&Bs[bRow][bCol] = b4;
        __syncthreads();

        #pragma unroll
        for (int kk = 0; kk < 8; kk++) {
            float ra[8], rb[8];
            *(float4*)&ra[0] = *(const float4*)&As[kk][ty * 8];
            *(float4*)&ra[4] = *(const float4*)&As[kk][ty * 8 + 4];
            *(float4*)&rb[0] = *(const float4*)&Bs[kk][tx * 8];
            *(float4*)&rb[4] = *(const float4*)&Bs[kk][tx * 8 + 4];
            #pragma unroll
            for (int i = 0; i < 8; i++)
                #pragma unroll
                for (int j = 0; j < 8; j++)
                    c[i][j] += ra[i] * rb[j];
        }
        __syncthreads();
    }

    float bb[8];
    *(float4*)&bb[0] = *(const float4*)(bias + n0 + tx * 8);
    *(float4*)&bb[4] = *(const float4*)(bias + n0 + tx * 8 + 4);

    #pragma unroll
    for (int i = 0; i < 8; i++) {
        int row = m0 + ty * 8 + i;
        float* Crow = C + (size_t)row * N + n0 + tx * 8;
        float v[8];
        #pragma unroll
        for (int j = 0; j < 8; j++) v[j] = c[i][j] + bb[j];
        if (EPI == 1) {
            #pragma unroll
            for (int j = 0; j < 8; j++) v[j] = fmaxf(v[j], 0.f);
        }
        if (EPI == 2) {
            const float* Rrow = res + (size_t)row * N + n0 + tx * 8;
            float r[8];
            *(float4*)&r[0] = *(const float4*)(Rrow);
            *(float4*)&r[4] = *(const float4*)(Rrow + 4);
            #pragma unroll
            for (int j = 0; j < 8; j++) v[j] += r[j];
        }
        *(float4*)(Crow)     = *(float4*)&v[0];
        *(float4*)(Crow + 4) = *(float4*)&v[4];
    }
}

// ---------------- Flash attention (non-causal), 64x64 tiles ------------------
// grid: (S/64, B*H); block 256 threads; dynamic smem = 3*64*65*4 bytes.
// q/k/v layout: t[(s*B + b)*D + h*64 + d]
#define ATTN_SMEM (3 * 64 * 65 * 4)

__global__ void __launch_bounds__(256, 3)
attn_kernel(const float* __restrict__ q, const float* __restrict__ k,
            const float* __restrict__ v, float* __restrict__ ctx) {
    extern __shared__ float sm[];
    float* Qs  = sm;             // [64][65]
    float* Ss  = sm + 64 * 65;   // [64][65]
    float* KVs = sm + 2 * 64 * 65;

    const int bh = blockIdx.y;
    const int b = bh / H_, h = bh % H_;
    const int qt = blockIdx.x;
    const int tid = threadIdx.x;
    const int tx = tid & 15, ty = tid >> 4;
    const float scale = rsqrtf((float)DH_);

    // load Q tile (scaled)
    for (int i = tid; i < 64 * 16; i += 256) {
        int r = i >> 4, d4 = (i & 15) << 2;
        float4 qv = *(const float4*)(q + ((size_t)(qt * 64 + r) * B_ + b) * D_ + h * 64 + d4);
        qv.x *= scale; qv.y *= scale; qv.z *= scale; qv.w *= scale;
        float* dst = &Qs[r * 65 + d4];
        dst[0] = qv.x; dst[1] = qv.y; dst[2] = qv.z; dst[3] = qv.w;
    }

    float mrun[4], lrun[4], Oacc[4][4];
    #pragma unroll
    for (int i = 0; i < 4; i++) {
        mrun[i] = -1e30f; lrun[i] = 0.f;
        #pragma unroll
        for (int j = 0; j < 4; j++) Oacc[i][j] = 0.f;
    }

    for (int kt = 0; kt < S_ / 64; kt++) {
        // load K tile into KVs
        __syncthreads();
        for (int i = tid; i < 64 * 16; i += 256) {
            int r = i >> 4, d4 = (i & 15) << 2;
            float4 kv = *(const float4*)(k + ((size_t)(kt * 64 + r) * B_ + b) * D_ + h * 64 + d4);
            float* dst = &KVs[r * 65 + d4];
            dst[0] = kv.x; dst[1] = kv.y; dst[2] = kv.z; dst[3] = kv.w;
        }
        __syncthreads();

        // s[i][j] = Q[ty*4+i] . K[tx*4+j]
        float s[4][4];
        #pragma unroll
        for (int i = 0; i < 4; i++)
            #pragma unroll
            for (int j = 0; j < 4; j++) s[i][j] = 0.f;

        #pragma unroll 8
        for (int d = 0; d < 64; d++) {
            float qr[4], kr[4];
            #pragma unroll
            for (int i = 0; i < 4; i++) qr[i] = Qs[(ty * 4 + i) * 65 + d];
            #pragma unroll
            for (int j = 0; j < 4; j++) kr[j] = KVs[(tx * 4 + j) * 65 + d];
            #pragma unroll
            for (int i = 0; i < 4; i++)
                #pragma unroll
                for (int j = 0; j < 4; j++) s[i][j] += qr[i] * kr[j];
        }

        // online softmax per row; write P to Ss
        #pragma unroll
        for (int i = 0; i < 4; i++) {
            float tm = fmaxf(fmaxf(s[i][0], s[i][1]), fmaxf(s[i][2], s[i][3]));
            #pragma unroll
            for (int o = 8; o; o >>= 1)
                tm = fmaxf(tm, __shfl_xor_sync(0xffffffffu, tm, o, 16));
            float newm = fmaxf(mrun[i], tm);
            float corr = __expf(mrun[i] - newm);
            mrun[i] = newm;
            float ls = 0.f;
            float p[4];
            #pragma unroll
            for (int j = 0; j < 4; j++) { p[j] = __expf(s[i][j] - newm); ls += p[j]; }
            #pragma unroll
            for (int o = 8; o; o >>= 1)
                ls += __shfl_xor_sync(0xffffffffu, ls, o, 16);
            lrun[i] = lrun[i] * corr + ls;
            #pragma unroll
            for (int j = 0; j < 4; j++) Oacc[i][j] *= corr;
            #pragma unroll
            for (int j = 0; j < 4; j++) Ss[(ty * 4 + i) * 65 + tx * 4 + j] = p[j];
        }
        __syncthreads();

        // load V tile into KVs (K no longer needed)
        for (int i = tid; i < 64 * 16; i += 256) {
            int r = i >> 4, d4 = (i & 15) << 2;
            float4 vv = *(const float4*)(v + ((size_t)(kt * 64 + r) * B_ + b) * D_ + h * 64 + d4);
            float* dst = &KVs[r * 65 + d4];
            dst[0] = vv.x; dst[1] = vv.y; dst[2] = vv.z; dst[3] = vv.w;
        }
        __syncthreads();

        // O += P @ V
        #pragma unroll 8
        for (int cc = 0; cc < 64; cc++) {
            float pr[4], vr[4];
            #pragma unroll
            for (int i = 0; i < 4; i++) pr[i] = Ss[(ty * 4 + i) * 65 + cc];
            #pragma unroll
            for (int j = 0; j < 4; j++) vr[j] = KVs[cc * 65 + tx * 4 + j];
            #pragma unroll
            for (int i = 0; i < 4; i++)
                #pragma unroll
                for (int j = 0; j < 4; j++) Oacc[i][j] += pr[i] * vr[j];
        }
    }

    // final normalize + store
    #pragma unroll
    for (int i = 0; i < 4; i++) {
        float invl = 1.0f / lrun[i];
        float4 o;
        o.x = Oacc[i][0] * invl; o.y = Oacc[i][1] * invl;
        o.z = Oacc[i][2] * invl; o.w = Oacc[i][3] * invl;
        *(float4*)(ctx + ((size_t)(qt * 64 + ty * 4 + i) * B_ + b) * D_ + h * 64 + tx * 4) = o;
    }
}

// ---------------- launch ------------------------------------------------------
extern "C" void kernel_launch(void* const* d_in, const int* in_sizes, int n_in,
                              void* d_out, int out_size) {
    const float* x     = (const float*)d_in[0];
    const float* ln1_g = (const float*)d_in[1];
    const float* ln1_b = (const float*)d_in[2];
    const float* ln2_g = (const float*)d_in[3];
    const float* ln2_b = (const float*)d_in[4];
    const float* Wq    = (const float*)d_in[5];
    const float* bq    = (const float*)d_in[6];
    const float* Wk    = (const float*)d_in[7];
    const float* bk    = (const float*)d_in[8];
    const float* Wv    = (const float*)d_in[9];
    const float* bv    = (const float*)d_in[10];
    const float* Wo    = (const float*)d_in[11];
    const float* bo    = (const float*)d_in[12];
    const float* W1    = (const float*)d_in[13];
    const float* b1    = (const float*)d_in[14];
    const float* W2    = (const float*)d_in[15];
    const float* b2    = (const float*)d_in[16];
    float* out = (float*)d_out;

    float *ph, *pq, *pk, *pv, *pctx, *px1, *ph2, *pff;
    cudaGetSymbolAddress((void**)&ph,  g_h);
    cudaGetSymbolAddress((void**)&pq,  g_q);
    cudaGetSymbolAddress((void**)&pk,  g_k);
    cudaGetSymbolAddress((void**)&pv,  g_v);
    cudaGetSymbolAddress((void**)&pctx,g_ctx);
    cudaGetSymbolAddress((void**)&px1, g_x1);
    cudaGetSymbolAddress((void**)&ph2, g_h2);
    cudaGetSymbolAddress((void**)&pff, g_ff);

    cudaFuncSetAttribute(attn_kernel, cudaFuncAttributeMaxDynamicSharedMemorySize, ATTN_SMEM);

    // 1. h = LN1(x)
    ln_kernel<<<M_, 256>>>(x, ln1_g, ln1_b, ph);

    // 2-4. q/k/v = h @ W + b
    dim3 gD(D_ / 128, M_ / 128);
    gemm_kernel<0><<<gD, 256>>>(ph, Wq, bq, nullptr, pq, M_, D_, D_);
    gemm_kernel<0><<<gD, 256>>>(ph, Wk, bk, nullptr, pk, M_, D_, D_);
    gemm_kernel<0><<<gD, 256>>>(ph, Wv, bv, nullptr, pv, M_, D_, D_);

    // 5. flash attention -> ctx
    attn_kernel<<<dim3(S_ / 64, B_ * H_), 256, ATTN_SMEM>>>(pq, pk, pv, pctx);

    // 6. x1 = x + ctx @ Wo + bo
    gemm_kernel<2><<<gD, 256>>>(pctx, Wo, bo, x, px1, M_, D_, D_);

    // 7. h2 = LN2(x1)
    ln_kernel<<<M_, 256>>>(px1, ln2_g, ln2_b, ph2);

    // 8. ff = relu(h2 @ W1 + b1)
    dim3 gF(F_ / 128, M_ / 128);
    gemm_kernel<1><<<gF, 256>>>(ph2, W1, b1, nullptr, pff, M_, F_, D_);

    // 9. out = x1 + ff @ W2 + b2
    gemm_kernel<2><<<gD, 256>>>(pff, W2, b2, px1, out, M_, D_, F_);
}

// round 7
// speedup vs baseline: 1.9271x; 1.9271x over previous
#include <cuda_runtime.h>
#include <cstdint>
#include <math.h>

#define S_  2048
#define B_  4
#define D_  1024
#define H_  16
#define DH_ 64
#define F_  4096
#define M_  8192   // S_*B_

// ---------------- scratch (device globals; no allocation allowed) ------------
__device__ float g_h  [M_ * D_];
__device__ float g_q  [M_ * D_];
__device__ float g_k  [M_ * D_];
__device__ float g_v  [M_ * D_];
__device__ float g_ctx[M_ * D_];
__device__ float g_x1 [M_ * D_];
__device__ float g_h2 [M_ * D_];
__device__ float g_ff [(size_t)M_ * F_];
// transposed (+tf32-rounded) weights, [N, K] K-major
__device__ float g_wqT[D_ * D_];
__device__ float g_wkT[D_ * D_];
__device__ float g_wvT[D_ * D_];
__device__ float g_woT[D_ * D_];
__device__ float g_w1T[(size_t)F_ * D_];   // [4096,1024]
__device__ float g_w2T[(size_t)D_ * F_];   // [1024,4096]

// ---------------- helpers -----------------------------------------------------
__device__ __forceinline__ uint32_t smem_u32(const void* p) {
    uint32_t a;
    asm("{ .reg .u64 t; cvta.to.shared.u64 t, %1; cvt.u32.u64 %0, t; }" : "=r"(a) : "l"(p));
    return a;
}
__device__ __forceinline__ float tf32rn(float x) {
    float r;
    asm("cvt.rna.tf32.f32 %0, %1;" : "=f"(r) : "f"(x));
    return r;
}
#define CP_ASYNC16(dst, src) \
    asm volatile("cp.async.cg.shared.global [%0], [%1], 16;" :: "r"(dst), "l"(src))
#define CP_COMMIT() asm volatile("cp.async.commit_group;" ::: "memory")

__device__ __forceinline__ void mma_tf32(float* c, const uint32_t* a, const uint32_t* b) {
    asm volatile(
        "mma.sync.aligned.m16n8k8.row.col.f32.tf32.tf32.f32 "
        "{%0,%1,%2,%3}, {%4,%5,%6,%7}, {%8,%9}, {%0,%1,%2,%3};"
        : "+f"(c[0]), "+f"(c[1]), "+f"(c[2]), "+f"(c[3])
        : "r"(a[0]), "r"(a[1]), "r"(a[2]), "r"(a[3]), "r"(b[0]), "r"(b[1]));
}

// ---------------- tf32 mma.sync GEMM ------------------------------------------
// C[M,N] = A[M,K] @ Bt[N,K]^T (+bias / relu+round / +residual)
// 128x128 tile, 256 thr (8 warps 2x4, warp tile 64x32), K-chunk 32, 3-stage cp.async.
#define TM    128
#define TN    128
#define TK    32
#define NSTG  3
#define LDSD  36                     // smem row stride (floats) -> conflict-free frags
#define TILEF (128 * LDSD)           // floats per (A or B) stage
#define GEMM_SMEM (NSTG * 2 * TILEF * 4)   // 110592 bytes

template<int EPI>  // 0: +bias   1: round(relu(+bias))   2: +bias +residual
__global__ void __launch_bounds__(256, 1)
gemm_mma(const float* __restrict__ A, const float* __restrict__ Bt,
         const float* __restrict__ bias, const float* __restrict__ res,
         float* __restrict__ C, int N, int K) {
    extern __shared__ float sm[];
    float* As = sm;
    float* Bs = sm + NSTG * TILEF;

    const int tid  = threadIdx.x;
    const int lane = tid & 31, wid = tid >> 5;
    const int wm = wid & 1, wn = wid >> 1;          // warp grid 2(M) x 4(N)
    const int m0 = blockIdx.y * TM, n0 = blockIdx.x * TN;
    const int g = lane >> 2, t = lane & 3;
    const int CH = K / TK;

    float c[4][4][4];
    #pragma unroll
    for (int i = 0; i < 4; i++)
        #pragma unroll
        for (int j = 0; j < 4; j++)
            #pragma unroll
            for (int r = 0; r < 4; r++) c[i][j][r] = 0.f;

    // stage loader: 128 rows x 8 granules(16B) for each of A,B; 256 thr x 4 granules
    auto load_stage = [&](int cc, int s) {
        const float* Ab = A  + (size_t)m0 * K + cc * TK;
        const float* Bb = Bt + (size_t)n0 * K + cc * TK;
        float* as = As + s * TILEF;
        float* bs = Bs + s * TILEF;
        #pragma unroll
        for (int i = 0; i < 4; i++) {
            int gi = tid + 256 * i;           // 0..1023
            int r = gi >> 3, gc = gi & 7;
            CP_ASYNC16(smem_u32(as + r * LDSD + gc * 4), Ab + (size_t)r * K + gc * 4);
            CP_ASYNC16(smem_u32(bs + r * LDSD + gc * 4), Bb + (size_t)r * K + gc * 4);
        }
        CP_COMMIT();
    };

    load_stage(0, 0);
    load_stage(1, 1);

    for (int cc = 0; cc < CH; cc++) {
        if (cc == CH - 1) asm volatile("cp.async.wait_group 0;" ::: "memory");
        else              asm volatile("cp.async.wait_group 1;" ::: "memory");
        __syncthreads();

        if (cc + 2 < CH) load_stage(cc + 2, (cc + 2) % NSTG);

        const float* as = As + (cc % NSTG) * TILEF + (wm * 64) * LDSD;
        const float* bs = Bs + (cc % NSTG) * TILEF + (wn * 32) * LDSD;

        #pragma unroll
        for (int s = 0; s < 4; s++) {              // 4 k-steps of 8
            const int k0 = s * 8;
            uint32_t af[4][4], bf[4][2];
            #pragma unroll
            for (int i = 0; i < 4; i++) {
                const uint32_t* ap = (const uint32_t*)(as + (i * 16 + g) * LDSD + k0 + t);
                af[i][0] = ap[0];
                af[i][1] = ap[8 * LDSD];
                af[i][2] = ap[4];
                af[i][3] = ap[8 * LDSD + 4];
            }
            #pragma unroll
            for (int j = 0; j < 4; j++) {
                const uint32_t* bp = (const uint32_t*)(bs + (j * 8 + g) * LDSD + k0 + t);
                bf[j][0] = bp[0];
                bf[j][1] = bp[4];
            }
            #pragma unroll
            for (int i = 0; i < 4; i++)
                #pragma unroll
                for (int j = 0; j < 4; j++)
                    mma_tf32(c[i][j], af[i], bf[j]);
        }
    }

    // ---------------- epilogue -------------------------------------------------
    #pragma unroll
    for (int i = 0; i < 4; i++) {
        const int r0 = m0 + wm * 64 + i * 16 + g;
        #pragma unroll
        for (int j = 0; j < 4; j++) {
            const int col = n0 + wn * 32 + j * 8 + 2 * t;
            float b0 = bias[col], b1 = bias[col + 1];
            float v0 = c[i][j][0] + b0, v1 = c[i][j][1] + b1;
            float v2 = c[i][j][2] + b0, v3 = c[i][j][3] + b1;
            if (EPI == 1) {
                v0 = tf32rn(fmaxf(v0, 0.f)); v1 = tf32rn(fmaxf(v1, 0.f));
                v2 = tf32rn(fmaxf(v2, 0.f)); v3 = tf32rn(fmaxf(v3, 0.f));
            }
            if (EPI == 2) {
                float2 ra = *(const float2*)(res + (size_t)r0 * N + col);
                float2 rb = *(const float2*)(res + (size_t)(r0 + 8) * N + col);
                v0 += ra.x; v1 += ra.y; v2 += rb.x; v3 += rb.y;
            }
            *(float2*)(C + (size_t)r0 * N + col)       = make_float2(v0, v1);
            *(float2*)(C + (size_t)(r0 + 8) * N + col) = make_float2(v2, v3);
        }
    }
}

// ---------------- weight transpose + tf32-RN round ----------------------------
__global__ void transpose_round(const float* __restrict__ in, float* __restrict__ out,
                                int K, int N) {
    __shared__ float t[32][33];
    int n0 = blockIdx.x * 32, k0 = blockIdx.y * 32;
    #pragma unroll
    for (int i = threadIdx.y; i < 32; i += 8)
        t[i][threadIdx.x] = in[(size_t)(k0 + i) * N + n0 + threadIdx.x];
    __syncthreads();
    #pragma unroll
    for (int i = threadIdx.y; i < 32; i += 8)
        out[(size_t)(n0 + i) * K + k0 + threadIdx.x] = tf32rn(t[threadIdx.x][i]);
}

// ---------------- block reduction --------------------------------------------
__device__ __forceinline__ float blockReduceSum256(float val) {
    __shared__ float sh[8];
    #pragma unroll
    for (int o = 16; o; o >>= 1) val += __shfl_xor_sync(0xffffffffu, val, o);
    int w = threadIdx.x >> 5;
    if ((threadIdx.x & 31) == 0) sh[w] = val;
    __syncthreads();
    float tot = 0.f;
    #pragma unroll
    for (int i = 0; i < 8; i++) tot += sh[i];
    __syncthreads();
    return tot;
}

// ---------------- LayerNorm (output rounded to tf32 — feeds GEMMs only) ------
__global__ void ln_kernel(const float* __restrict__ x,
                          const float* __restrict__ g,
                          const float* __restrict__ b,
                          float* __restrict__ out) {
    int row = blockIdx.x;
    const float4* xr = (const float4*)(x + (size_t)row * D_);
    float4 xv = xr[threadIdx.x];

    float s = xv.x + xv.y + xv.z + xv.w;
    float mean = blockReduceSum256(s) * (1.0f / D_);

    float dx0 = xv.x - mean, dx1 = xv.y - mean, dx2 = xv.z - mean, dx3 = xv.w - mean;
    float s2 = dx0*dx0 + dx1*dx1 + dx2*dx2 + dx3*dx3;
    float var = blockReduceSum256(s2) * (1.0f / D_);
    float inv = rsqrtf(var + 1e-5f);

    float4 gv = ((const float4*)g)[threadIdx.x];
    float4 bv = ((const float4*)b)[threadIdx.x];
    float4 o;
    o.x = tf32rn(dx0 * inv * gv.x + bv.x);
    o.y = tf32rn(dx1 * inv * gv.y + bv.y);
    o.z = tf32rn(dx2 * inv * gv.z + bv.z);
    o.w = tf32rn(dx3 * inv * gv.w + bv.w);
    ((float4*)(out + (size_t)row * D_))[threadIdx.x] = o;
}

// ---------------- Flash attention (fp32, ctx output rounded to tf32) ----------
#define ATTN_SMEM (3 * 64 * 65 * 4)

__global__ void __launch_bounds__(256, 3)
attn_kernel(const float* __restrict__ q, const float* __restrict__ k,
            const float* __restrict__ v, float* __restrict__ ctx) {
    extern __shared__ float sm[];
    float* Qs  = sm;
    float* Ss  = sm + 64 * 65;
    float* KVs = sm + 2 * 64 * 65;

    const int bh = blockIdx.y;
    const int b = bh / H_, h = bh % H_;
    const int qt = blockIdx.x;
    const int tid = threadIdx.x;
    const int tx = tid & 15, ty = tid >> 4;
    const float scale = rsqrtf((float)DH_);

    for (int i = tid; i < 64 * 16; i += 256) {
        int r = i >> 4, d4 = (i & 15) << 2;
        float4 qv = *(const float4*)(q + ((size_t)(qt * 64 + r) * B_ + b) * D_ + h * 64 + d4);
        qv.x *= scale; qv.y *= scale; qv.z *= scale; qv.w *= scale;
        float* dst = &Qs[r * 65 + d4];
        dst[0] = qv.x; dst[1] = qv.y; dst[2] = qv.z; dst[3] = qv.w;
    }

    float mrun[4], lrun[4], Oacc[4][4];
    #pragma unroll
    for (int i = 0; i < 4; i++) {
        mrun[i] = -1e30f; lrun[i] = 0.f;
        #pragma unroll
        for (int j = 0; j < 4; j++) Oacc[i][j] = 0.f;
    }

    for (int kt = 0; kt < S_ / 64; kt++) {
        __syncthreads();
        for (int i = tid; i < 64 * 16; i += 256) {
            int r = i >> 4, d4 = (i & 15) << 2;
            float4 kv = *(const float4*)(k + ((size_t)(kt * 64 + r) * B_ + b) * D_ + h * 64 + d4);
            float* dst = &KVs[r * 65 + d4];
            dst[0] = kv.x; dst[1] = kv.y; dst[2] = kv.z; dst[3] = kv.w;
        }
        __syncthreads();

        float s[4][4];
        #pragma unroll
        for (int i = 0; i < 4; i++)
            #pragma unroll
            for (int j = 0; j < 4; j++) s[i][j] = 0.f;

        #pragma unroll 8
        for (int d = 0; d < 64; d++) {
            float qr[4], kr[4];
            #pragma unroll
            for (int i = 0; i < 4; i++) qr[i] = Qs[(ty * 4 + i) * 65 + d];
            #pragma unroll
            for (int j = 0; j < 4; j++) kr[j] = KVs[(tx * 4 + j) * 65 + d];
            #pragma unroll
            for (int i = 0; i < 4; i++)
                #pragma unroll
                for (int j = 0; j < 4; j++) s[i][j] += qr[i] * kr[j];
        }

        #pragma unroll
        for (int i = 0; i < 4; i++) {
            float tm = fmaxf(fmaxf(s[i][0], s[i][1]), fmaxf(s[i][2], s[i][3]));
            #pragma unroll
            for (int o = 8; o; o >>= 1)
                tm = fmaxf(tm, __shfl_xor_sync(0xffffffffu, tm, o, 16));
            float newm = fmaxf(mrun[i], tm);
            float corr = __expf(mrun[i] - newm);
            mrun[i] = newm;
            float ls = 0.f;
            float p[4];
            #pragma unroll
            for (int j = 0; j < 4; j++) { p[j] = __expf(s[i][j] - newm); ls += p[j]; }
            #pragma unroll
            for (int o = 8; o; o >>= 1)
                ls += __shfl_xor_sync(0xffffffffu, ls, o, 16);
            lrun[i] = lrun[i] * corr + ls;
            #pragma unroll
            for (int j = 0; j < 4; j++) Oacc[i][j] *= corr;
            #pragma unroll
            for (int j = 0; j < 4; j++) Ss[(ty * 4 + i) * 65 + tx * 4 + j] = p[j];
        }
        __syncthreads();

        for (int i = tid; i < 64 * 16; i += 256) {
            int r = i >> 4, d4 = (i & 15) << 2;
            float4 vv = *(const float4*)(v + ((size_t)(kt * 64 + r) * B_ + b) * D_ + h * 64 + d4);
            float* dst = &KVs[r * 65 + d4];
            dst[0] = vv.x; dst[1] = vv.y; dst[2] = vv.z; dst[3] = vv.w;
        }
        __syncthreads();

        #pragma unroll 8
        for (int cc = 0; cc < 64; cc++) {
            float pr[4], vr[4];
            #pragma unroll
            for (int i = 0; i < 4; i++) pr[i] = Ss[(ty * 4 + i) * 65 + cc];
            #pragma unroll
            for (int j = 0; j < 4; j++) vr[j] = KVs[cc * 65 + tx * 4 + j];
            #pragma unroll
            for (int i = 0; i < 4; i++)
                #pragma unroll
                for (int j = 0; j < 4; j++) Oacc[i][j] += pr[i] * vr[j];
        }
    }

    #pragma unroll
    for (int i = 0; i < 4; i++) {
        float invl = 1.0f / lrun[i];
        float4 o;
        o.x = tf32rn(Oacc[i][0] * invl); o.y = tf32rn(Oacc[i][1] * invl);
        o.z = tf32rn(Oacc[i][2] * invl); o.w = tf32rn(Oacc[i][3] * invl);
        *(float4*)(ctx + ((size_t)(qt * 64 + ty * 4 + i) * B_ + b) * D_ + h * 64 + tx * 4) = o;
    }
}

// ---------------- launch ------------------------------------------------------
extern "C" void kernel_launch(void* const* d_in, const int* in_sizes, int n_in,
                              void* d_out, int out_size) {
    const float* x     = (const float*)d_in[0];
    const float* ln1_g = (const float*)d_in[1];
    const float* ln1_b = (const float*)d_in[2];
    const float* ln2_g = (const float*)d_in[3];
    const float* ln2_b = (const float*)d_in[4];
    const float* Wq    = (const float*)d_in[5];
    const float* bq    = (const float*)d_in[6];
    const float* Wk    = (const float*)d_in[7];
    const float* bk    = (const float*)d_in[8];
    const float* Wv    = (const float*)d_in[9];
    const float* bv    = (const float*)d_in[10];
    const float* Wo    = (const float*)d_in[11];
    const float* bo    = (const float*)d_in[12];
    const float* W1    = (const float*)d_in[13];
    const float* b1    = (const float*)d_in[14];
    const float* W2    = (const float*)d_in[15];
    const float* b2    = (const float*)d_in[16];
    float* out = (float*)d_out;

    float *ph, *pq, *pk, *pv, *pctx, *px1, *ph2, *pff;
    float *wqT, *wkT, *wvT, *woT, *w1T, *w2T;
    cudaGetSymbolAddress((void**)&ph,  g_h);
    cudaGetSymbolAddress((void**)&pq,  g_q);
    cudaGetSymbolAddress((void**)&pk,  g_k);
    cudaGetSymbolAddress((void**)&pv,  g_v);
    cudaGetSymbolAddress((void**)&pctx,g_ctx);
    cudaGetSymbolAddress((void**)&px1, g_x1);
    cudaGetSymbolAddress((void**)&ph2, g_h2);
    cudaGetSymbolAddress((void**)&pff, g_ff);
    cudaGetSymbolAddress((void**)&wqT, g_wqT);
    cudaGetSymbolAddress((void**)&wkT, g_wkT);
    cudaGetSymbolAddress((void**)&wvT, g_wvT);
    cudaGetSymbolAddress((void**)&woT, g_woT);
    cudaGetSymbolAddress((void**)&w1T, g_w1T);
    cudaGetSymbolAddress((void**)&w2T, g_w2T);

    cudaFuncSetAttribute(attn_kernel, cudaFuncAttributeMaxDynamicSharedMemorySize, ATTN_SMEM);
    cudaFuncSetAttribute(gemm_mma<0>, cudaFuncAttributeMaxDynamicSharedMemorySize, GEMM_SMEM);
    cudaFuncSetAttribute(gemm_mma<1>, cudaFuncAttributeMaxDynamicSharedMemorySize, GEMM_SMEM);
    cudaFuncSetAttribute(gemm_mma<2>, cudaFuncAttributeMaxDynamicSharedMemorySize, GEMM_SMEM);

    // 0. transpose + round weights to [N,K]
    dim3 tb(32, 8);
    transpose_round<<<dim3(D_/32, D_/32), tb>>>(Wq, wqT, D_, D_);
    transpose_round<<<dim3(D_/32, D_/32), tb>>>(Wk, wkT, D_, D_);
    transpose_round<<<dim3(D_/32, D_/32), tb>>>(Wv, wvT, D_, D_);
    transpose_round<<<dim3(D_/32, D_/32), tb>>>(Wo, woT, D_, D_);
    transpose_round<<<dim3(F_/32, D_/32), tb>>>(W1, w1T, D_, F_);
    transpose_round<<<dim3(D_/32, F_/32), tb>>>(W2, w2T, F_, D_);

    // 1. h = round(LN1(x))
    ln_kernel<<<M_, 256>>>(x, ln1_g, ln1_b, ph);

    // 2-4. q/k/v = h @ Wq/k/v + b   (tf32 mma.sync)
    dim3 gD(D_ / TN, M_ / TM);
    gemm_mma<0><<<gD, 256, GEMM_SMEM>>>(ph, wqT, bq, nullptr, pq, D_, D_);
    gemm_mma<0><<<gD, 256, GEMM_SMEM>>>(ph, wkT, bk, nullptr, pk, D_, D_);
    gemm_mma<0><<<gD, 256, GEMM_SMEM>>>(ph, wvT, bv, nullptr, pv, D_, D_);

    // 5. flash attention -> ctx (rounded)
    attn_kernel<<<dim3(S_ / 64, B_ * H_), 256, ATTN_SMEM>>>(pq, pk, pv, pctx);

    // 6. x1 = x + ctx @ Wo + bo
    gemm_mma<2><<<gD, 256, GEMM_SMEM>>>(pctx, woT, bo, x, px1, D_, D_);

    // 7. h2 = round(LN2(x1))
    ln_kernel<<<M_, 256>>>(px1, ln2_g, ln2_b, ph2);

    // 8. ff = round(relu(h2 @ W1 + b1))
    dim3 gF(F_ / TN, M_ / TM);
    gemm_mma<1><<<gF, 256, GEMM_SMEM>>>(ph2, w1T, b1, nullptr, pff, F_, D_);

    // 9. out = x1 + ff @ W2 + b2
    gemm_mma<2><<<gD, 256, GEMM_SMEM>>>(pff, w2T, b2, px1, out, D_, F_);
}

// round 8
// speedup vs baseline: 3.1219x; 1.6200x over previous
#include <cuda_runtime.h>
#include <cstdint>
#include <math.h>

#define S_  2048
#define B_  4
#define D_  1024
#define H_  16
#define DH_ 64
#define F_  4096
#define M_  8192   // S_*B_

// ---------------- scratch (device globals; no allocation allowed) ------------
__device__ float g_h  [M_ * D_];
__device__ float g_q  [M_ * D_];
__device__ float g_k  [M_ * D_];
__device__ float g_v  [M_ * D_];
__device__ float g_ctx[M_ * D_];
__device__ float g_x1 [M_ * D_];
__device__ float g_h2 [M_ * D_];
__device__ float g_ff [(size_t)M_ * F_];
// transposed (+tf32-rounded) weights, [N, K] K-major
__device__ float g_wqT[D_ * D_];
__device__ float g_wkT[D_ * D_];
__device__ float g_wvT[D_ * D_];
__device__ float g_woT[D_ * D_];
__device__ float g_w1T[(size_t)F_ * D_];   // [4096,1024]
__device__ float g_w2T[(size_t)D_ * F_];   // [1024,4096]

// ---------------- helpers -----------------------------------------------------
__device__ __forceinline__ uint32_t smem_u32(const void* p) {
    uint32_t a;
    asm("{ .reg .u64 t; cvta.to.shared.u64 t, %1; cvt.u32.u64 %0, t; }" : "=r"(a) : "l"(p));
    return a;
}
__device__ __forceinline__ float tf32rn(float x) {
    float r;
    asm("cvt.rna.tf32.f32 %0, %1;" : "=f"(r) : "f"(x));
    return r;
}
#define CP_ASYNC16(dst, src) \
    asm volatile("cp.async.cg.shared.global [%0], [%1], 16;" :: "r"(dst), "l"(src))
#define CP_COMMIT() asm volatile("cp.async.commit_group;" ::: "memory")

__device__ __forceinline__ void mma_tf32(float* c, const uint32_t* a, const uint32_t* b) {
    asm volatile(
        "mma.sync.aligned.m16n8k8.row.col.f32.tf32.tf32.f32 "
        "{%0,%1,%2,%3}, {%4,%5,%6,%7}, {%8,%9}, {%0,%1,%2,%3};"
        : "+f"(c[0]), "+f"(c[1]), "+f"(c[2]), "+f"(c[3])
        : "r"(a[0]), "r"(a[1]), "r"(a[2]), "r"(a[3]), "r"(b[0]), "r"(b[1]));
}

// ---------------- tf32 mma.sync GEMM ------------------------------------------
// C[M,N] = A[M,K] @ Bt[N,K]^T (+epilogue)
// 128x128 tile, 256 thr (8 warps 2x4, warp tile 64x32), K-chunk 32, 3-stage cp.async.
#define TM    128
#define TN    128
#define TK    32
#define NSTG  3
#define LDSD  36
#define TILEF (128 * LDSD)
#define GEMM_SMEM (NSTG * 2 * TILEF * 4)   // 110592 bytes

// EPI: 0 +bias | 1 round(relu(+bias)) | 2 +bias+residual | 3 round((+bias)*alpha)
template<int EPI>
__global__ void __launch_bounds__(256, 1)
gemm_mma(const float* __restrict__ A, const float* __restrict__ Bt,
         const float* __restrict__ bias, const float* __restrict__ res,
         float* __restrict__ C, int N, int K, float alpha) {
    extern __shared__ float sm[];
    float* As = sm;
    float* Bs = sm + NSTG * TILEF;

    const int tid  = threadIdx.x;
    const int lane = tid & 31, wid = tid >> 5;
    const int wm = wid & 1, wn = wid >> 1;
    const int m0 = blockIdx.y * TM, n0 = blockIdx.x * TN;
    const int g = lane >> 2, t = lane & 3;
    const int CH = K / TK;

    float c[4][4][4];
    #pragma unroll
    for (int i = 0; i < 4; i++)
        #pragma unroll
        for (int j = 0; j < 4; j++)
            #pragma unroll
            for (int r = 0; r < 4; r++) c[i][j][r] = 0.f;

    auto load_stage = [&](int cc, int s) {
        const float* Ab = A  + (size_t)m0 * K + cc * TK;
        const float* Bb = Bt + (size_t)n0 * K + cc * TK;
        float* as = As + s * TILEF;
        float* bs = Bs + s * TILEF;
        #pragma unroll
        for (int i = 0; i < 4; i++) {
            int gi = tid + 256 * i;
            int r = gi >> 3, gc = gi & 7;
            CP_ASYNC16(smem_u32(as + r * LDSD + gc * 4), Ab + (size_t)r * K + gc * 4);
            CP_ASYNC16(smem_u32(bs + r * LDSD + gc * 4), Bb + (size_t)r * K + gc * 4);
        }
        CP_COMMIT();
    };

    load_stage(0, 0);
    load_stage(1, 1);

    for (int cc = 0; cc < CH; cc++) {
        if (cc == CH - 1) asm volatile("cp.async.wait_group 0;" ::: "memory");
        else              asm volatile("cp.async.wait_group 1;" ::: "memory");
        __syncthreads();

        if (cc + 2 < CH) load_stage(cc + 2, (cc + 2) % NSTG);

        const float* as = As + (cc % NSTG) * TILEF + (wm * 64) * LDSD;
        const float* bs = Bs + (cc % NSTG) * TILEF + (wn * 32) * LDSD;

        #pragma unroll
        for (int s = 0; s < 4; s++) {
            const int k0 = s * 8;
            uint32_t af[4][4], bf[4][2];
            #pragma unroll
            for (int i = 0; i < 4; i++) {
                const uint32_t* ap = (const uint32_t*)(as + (i * 16 + g) * LDSD + k0 + t);
                af[i][0] = ap[0];
                af[i][1] = ap[8 * LDSD];
                af[i][2] = ap[4];
                af[i][3] = ap[8 * LDSD + 4];
            }
            #pragma unroll
            for (int j = 0; j < 4; j++) {
                const uint32_t* bp = (const uint32_t*)(bs + (j * 8 + g) * LDSD + k0 + t);
                bf[j][0] = bp[0];
                bf[j][1] = bp[4];
            }
            #pragma unroll
            for (int i = 0; i < 4; i++)
                #pragma unroll
                for (int j = 0; j < 4; j++)
                    mma_tf32(c[i][j], af[i], bf[j]);
        }
    }

    #pragma unroll
    for (int i = 0; i < 4; i++) {
        const int r0 = m0 + wm * 64 + i * 16 + g;
        #pragma unroll
        for (int j = 0; j < 4; j++) {
            const int col = n0 + wn * 32 + j * 8 + 2 * t;
            float b0 = bias[col], b1 = bias[col + 1];
            float v0 = c[i][j][0] + b0, v1 = c[i][j][1] + b1;
            float v2 = c[i][j][2] + b0, v3 = c[i][j][3] + b1;
            if (EPI == 1) {
                v0 = tf32rn(fmaxf(v0, 0.f)); v1 = tf32rn(fmaxf(v1, 0.f));
                v2 = tf32rn(fmaxf(v2, 0.f)); v3 = tf32rn(fmaxf(v3, 0.f));
            }
            if (EPI == 2) {
                float2 ra = *(const float2*)(res + (size_t)r0 * N + col);
                float2 rb = *(const float2*)(res + (size_t)(r0 + 8) * N + col);
                v0 += ra.x; v1 += ra.y; v2 += rb.x; v3 += rb.y;
            }
            if (EPI == 3) {
                v0 = tf32rn(v0 * alpha); v1 = tf32rn(v1 * alpha);
                v2 = tf32rn(v2 * alpha); v3 = tf32rn(v3 * alpha);
            }
            *(float2*)(C + (size_t)r0 * N + col)       = make_float2(v0, v1);
            *(float2*)(C + (size_t)(r0 + 8) * N + col) = make_float2(v2, v3);
        }
    }
}

// ---------------- weight transpose + tf32-RN round ----------------------------
__global__ void transpose_round(const float* __restrict__ in, float* __restrict__ out,
                                int K, int N) {
    __shared__ float t[32][33];
    int n0 = blockIdx.x * 32, k0 = blockIdx.y * 32;
    #pragma unroll
    for (int i = threadIdx.y; i < 32; i += 8)
        t[i][threadIdx.x] = in[(size_t)(k0 + i) * N + n0 + threadIdx.x];
    __syncthreads();
    #pragma unroll
    for (int i = threadIdx.y; i < 32; i += 8)
        out[(size_t)(n0 + i) * K + k0 + threadIdx.x] = tf32rn(t[threadIdx.x][i]);
}

// ---------------- block reduction --------------------------------------------
__device__ __forceinline__ float blockReduceSum256(float val) {
    __shared__ float sh[8];
    #pragma unroll
    for (int o = 16; o; o >>= 1) val += __shfl_xor_sync(0xffffffffu, val, o);
    int w = threadIdx.x >> 5;
    if ((threadIdx.x & 31) == 0) sh[w] = val;
    __syncthreads();
    float tot = 0.f;
    #pragma unroll
    for (int i = 0; i < 8; i++) tot += sh[i];
    __syncthreads();
    return tot;
}

// ---------------- LayerNorm (output rounded to tf32 — feeds GEMMs only) ------
__global__ void ln_kernel(const float* __restrict__ x,
                          const float* __restrict__ g,
                          const float* __restrict__ b,
                          float* __restrict__ out) {
    int row = blockIdx.x;
    const float4* xr = (const float4*)(x + (size_t)row * D_);
    float4 xv = xr[threadIdx.x];

    float s = xv.x + xv.y + xv.z + xv.w;
    float mean = blockReduceSum256(s) * (1.0f / D_);

    float dx0 = xv.x - mean, dx1 = xv.y - mean, dx2 = xv.z - mean, dx3 = xv.w - mean;
    float s2 = dx0*dx0 + dx1*dx1 + dx2*dx2 + dx3*dx3;
    float var = blockReduceSum256(s2) * (1.0f / D_);
    float inv = rsqrtf(var + 1e-5f);

    float4 gv = ((const float4*)g)[threadIdx.x];
    float4 bv = ((const float4*)b)[threadIdx.x];
    float4 o;
    o.x = tf32rn(dx0 * inv * gv.x + bv.x);
    o.y = tf32rn(dx1 * inv * gv.y + bv.y);
    o.z = tf32rn(dx2 * inv * gv.z + bv.z);
    o.w = tf32rn(dx3 * inv * gv.w + bv.w);
    ((float4*)(out + (size_t)row * D_))[threadIdx.x] = o;
}

// ---------------- Flash attention with tf32 mma.sync ---------------------------
// grid (S/128, B*H), 256 thr (8 warps x 16 Q rows). q pre-scaled+rounded; k,v rounded.
// smem: Q[128][AST] + P[128][AST] + 3 KV stages of [128][AST] (K rows 0-63, V 64-127)
#define AST 68
#define NKT (S_ / 64)
#define ATT_SMEM (5 * 128 * AST * 4)   // 174080

__global__ void __launch_bounds__(256, 1)
attn_mma(const float* __restrict__ q, const float* __restrict__ k,
         const float* __restrict__ v, float* __restrict__ ctx) {
    extern __shared__ float sm[];
    float* Qs = sm;                    // [128][AST]
    float* Ps = sm + 128 * AST;        // [128][AST]
    float* KV = sm + 256 * AST;        // 3 x [128][AST]

    const int tid = threadIdx.x;
    const int lane = tid & 31, wid = tid >> 5;
    const int g = lane >> 2, t = lane & 3;
    const int bh = blockIdx.y, b = bh >> 4, h = bh & 15;
    const int qt = blockIdx.x;
    const int colbase = h * 64;

    auto issue_kv = [&](int kt) {
        float* st = KV + (kt % 3) * 128 * AST;
        #pragma unroll
        for (int j = 0; j < 8; j++) {
            int gi = tid + 256 * j;          // 0..2047
            int r = (gi & 1023) >> 4, c4 = (gi & 15) << 2;
            const float* src = (gi < 1024)
                ? k + ((size_t)(kt * 64 + r) * B_ + b) * D_ + colbase + c4
                : v + ((size_t)(kt * 64 + r) * B_ + b) * D_ + colbase + c4;
            float* dst = st + ((gi < 1024) ? r : (64 + r)) * AST + c4;
            CP_ASYNC16(smem_u32(dst), src);
        }
        CP_COMMIT();
    };
    issue_kv(0);
    issue_kv(1);

    // load Q tile (pre-scaled + tf32-rounded by GEMM epilogue)
    for (int i = tid; i < 128 * 16; i += 256) {
        int r = i >> 4, c4 = (i & 15) << 2;
        *(float4*)(Qs + r * AST + c4) =
            *(const float4*)(q + ((size_t)(qt * 128 + r) * B_ + b) * D_ + colbase + c4);
    }
    __syncthreads();

    // Q fragments, register-resident for the whole kernel
    uint32_t qf[8][4];
    {
        const uint32_t* q0 = (const uint32_t*)(Qs + (wid * 16 + g) * AST);
        const uint32_t* q1 = (const uint32_t*)(Qs + (wid * 16 + g + 8) * AST);
        #pragma unroll
        for (int kc = 0; kc < 8; kc++) {
            qf[kc][0] = q0[kc * 8 + t];
            qf[kc][1] = q1[kc * 8 + t];
            qf[kc][2] = q0[kc * 8 + t + 4];
            qf[kc][3] = q1[kc * 8 + t + 4];
        }
    }

    float mr[2] = {-1e30f, -1e30f}, lr[2] = {0.f, 0.f};
    float O[8][4];
    #pragma unroll
    for (int nt = 0; nt < 8; nt++)
        #pragma unroll
        for (int r = 0; r < 4; r++) O[nt][r] = 0.f;

    float* Pw0 = Ps + (wid * 16 + g) * AST;
    float* Pw1 = Ps + (wid * 16 + g + 8) * AST;

    for (int kt = 0; kt < NKT; kt++) {
        if (kt == NKT - 1) asm volatile("cp.async.wait_group 0;" ::: "memory");
        else               asm volatile("cp.async.wait_group 1;" ::: "memory");
        __syncthreads();
        if (kt + 2 < NKT) issue_kv(kt + 2);

        const float* Ks = KV + (kt % 3) * 128 * AST;
        const float* Vs = Ks + 64 * AST;

        // S = Q @ K^T   (warp: 16 q-rows x 64 keys)
        float s[8][4];
        #pragma unroll
        for (int nt = 0; nt < 8; nt++)
            #pragma unroll
            for (int r = 0; r < 4; r++) s[nt][r] = 0.f;

        #pragma unroll
        for (int kc = 0; kc < 8; kc++) {
            #pragma unroll
            for (int nt = 0; nt < 8; nt++) {
                const uint32_t* kp = (const uint32_t*)(Ks + (nt * 8 + g) * AST + kc * 8 + t);
                uint32_t bf[2] = { kp[0], kp[4] };
                mma_tf32(s[nt], qf[kc], bf);
            }
        }

        // online softmax (rows g and g+8)
        #pragma unroll
        for (int ro = 0; ro < 2; ro++) {
            float tmax = -1e30f;
            #pragma unroll
            for (int nt = 0; nt < 8; nt++)
                tmax = fmaxf(tmax, fmaxf(s[nt][2 * ro], s[nt][2 * ro + 1]));
            tmax = fmaxf(tmax, __shfl_xor_sync(0xffffffffu, tmax, 1));
            tmax = fmaxf(tmax, __shfl_xor_sync(0xffffffffu, tmax, 2));
            float newm = fmaxf(mr[ro], tmax);
            float corr = __expf(mr[ro] - newm);
            mr[ro] = newm;
            float sum = 0.f;
            float* Pw = ro ? Pw1 : Pw0;
            #pragma unroll
            for (int nt = 0; nt < 8; nt++) {
                float p0 = __expf(s[nt][2 * ro]     - newm);
                float p1 = __expf(s[nt][2 * ro + 1] - newm);
                sum += p0 + p1;
                *(float2*)(Pw + nt * 8 + 2 * t) = make_float2(tf32rn(p0), tf32rn(p1));
                O[nt][2 * ro]     *= corr;
                O[nt][2 * ro + 1] *= corr;
            }
            sum += __shfl_xor_sync(0xffffffffu, sum, 1);
            sum += __shfl_xor_sync(0xffffffffu, sum, 2);
            lr[ro] = lr[ro] * corr + sum;
        }
        __syncwarp();

        // O += P @ V
        #pragma unroll
        for (int kc = 0; kc < 8; kc++) {
            uint32_t pa[4];
            pa[0] = ((const uint32_t*)Pw0)[kc * 8 + t];
            pa[1] = ((const uint32_t*)Pw1)[kc * 8 + t];
            pa[2] = ((const uint32_t*)Pw0)[kc * 8 + t + 4];
            pa[3] = ((const uint32_t*)Pw1)[kc * 8 + t + 4];
            #pragma unroll
            for (int nt = 0; nt < 8; nt++) {
                uint32_t bf[2];
                bf[0] = *(const uint32_t*)(Vs + (kc * 8 + t) * AST + nt * 8 + g);
                bf[1] = *(const uint32_t*)(Vs + (kc * 8 + t + 4) * AST + nt * 8 + g);
                mma_tf32(O[nt], pa, bf);
            }
        }
        __syncwarp();
    }

    // normalize + store ctx (rounded: feeds Wo GEMM)
    float inv0 = 1.f / lr[0], inv1 = 1.f / lr[1];
    const int r0 = qt * 128 + wid * 16 + g;
    #pragma unroll
    for (int nt = 0; nt < 8; nt++) {
        int col = colbase + nt * 8 + 2 * t;
        *(float2*)(ctx + ((size_t)r0 * B_ + b) * D_ + col) =
            make_float2(tf32rn(O[nt][0] * inv0), tf32rn(O[nt][1] * inv0));
        *(float2*)(ctx + ((size_t)(r0 + 8) * B_ + b) * D_ + col) =
            make_float2(tf32rn(O[nt][2] * inv1), tf32rn(O[nt][3] * inv1));
    }
}

// ---------------- launch ------------------------------------------------------
extern "C" void kernel_launch(void* const* d_in, const int* in_sizes, int n_in,
                              void* d_out, int out_size) {
    const float* x     = (const float*)d_in[0];
    const float* ln1_g = (const float*)d_in[1];
    const float* ln1_b = (const float*)d_in[2];
    const float* ln2_g = (const float*)d_in[3];
    const float* ln2_b = (const float*)d_in[4];
    const float* Wq    = (const float*)d_in[5];
    const float* bq    = (const float*)d_in[6];
    const float* Wk    = (const float*)d_in[7];
    const float* bk    = (const float*)d_in[8];
    const float* Wv    = (const float*)d_in[9];
    const float* bv    = (const float*)d_in[10];
    const float* Wo    = (const float*)d_in[11];
    const float* bo    = (const float*)d_in[12];
    const float* W1    = (const float*)d_in[13];
    const float* b1    = (const float*)d_in[14];
    const float* W2    = (const float*)d_in[15];
    const float* b2    = (const float*)d_in[16];
    float* out = (float*)d_out;

    float *ph, *pq, *pk, *pv, *pctx, *px1, *ph2, *pff;
    float *wqT, *wkT, *wvT, *woT, *w1T, *w2T;
    cudaGetSymbolAddress((void**)&ph,  g_h);
    cudaGetSymbolAddress((void**)&pq,  g_q);
    cudaGetSymbolAddress((void**)&pk,  g_k);
    cudaGetSymbolAddress((void**)&pv,  g_v);
    cudaGetSymbolAddress((void**)&pctx,g_ctx);
    cudaGetSymbolAddress((void**)&px1, g_x1);
    cudaGetSymbolAddress((void**)&ph2, g_h2);
    cudaGetSymbolAddress((void**)&pff, g_ff);
    cudaGetSymbolAddress((void**)&wqT, g_wqT);
    cudaGetSymbolAddress((void**)&wkT, g_wkT);
    cudaGetSymbolAddress((void**)&wvT, g_wvT);
    cudaGetSymbolAddress((void**)&woT, g_woT);
    cudaGetSymbolAddress((void**)&w1T, g_w1T);
    cudaGetSymbolAddress((void**)&w2T, g_w2T);

    cudaFuncSetAttribute(attn_mma,    cudaFuncAttributeMaxDynamicSharedMemorySize, ATT_SMEM);
    cudaFuncSetAttribute(gemm_mma<0>, cudaFuncAttributeMaxDynamicSharedMemorySize, GEMM_SMEM);
    cudaFuncSetAttribute(gemm_mma<1>, cudaFuncAttributeMaxDynamicSharedMemorySize, GEMM_SMEM);
    cudaFuncSetAttribute(gemm_mma<2>, cudaFuncAttributeMaxDynamicSharedMemorySize, GEMM_SMEM);
    cudaFuncSetAttribute(gemm_mma<3>, cudaFuncAttributeMaxDynamicSharedMemorySize, GEMM_SMEM);

    // 0. transpose + round weights to [N,K]
    dim3 tb(32, 8);
    transpose_round<<<dim3(D_/32, D_/32), tb>>>(Wq, wqT, D_, D_);
    transpose_round<<<dim3(D_/32, D_/32), tb>>>(Wk, wkT, D_, D_);
    transpose_round<<<dim3(D_/32, D_/32), tb>>>(Wv, wvT, D_, D_);
    transpose_round<<<dim3(D_/32, D_/32), tb>>>(Wo, woT, D_, D_);
    transpose_round<<<dim3(F_/32, D_/32), tb>>>(W1, w1T, D_, F_);
    transpose_round<<<dim3(D_/32, F_/32), tb>>>(W2, w2T, F_, D_);

    // 1. h = round(LN1(x))
    ln_kernel<<<M_, 256>>>(x, ln1_g, ln1_b, ph);

    // 2-4. q/k/v (tf32 mma.sync); outputs tf32-rounded; Q pre-scaled by 1/sqrt(DH)
    dim3 gD(D_ / TN, M_ / TM);
    const float qscale = 0.125f;   // 1/sqrt(64)
    gemm_mma<3><<<gD, 256, GEMM_SMEM>>>(ph, wqT, bq, nullptr, pq, D_, D_, qscale);
    gemm_mma<3><<<gD, 256, GEMM_SMEM>>>(ph, wkT, bk, nullptr, pk, D_, D_, 1.0f);
    gemm_mma<3><<<gD, 256, GEMM_SMEM>>>(ph, wvT, bv, nullptr, pv, D_, D_, 1.0f);

    // 5. flash attention (tf32 mma) -> ctx (rounded)
    attn_mma<<<dim3(S_ / 128, B_ * H_), 256, ATT_SMEM>>>(pq, pk, pv, pctx);

    // 6. x1 = x + ctx @ Wo + bo
    gemm_mma<2><<<gD, 256, GEMM_SMEM>>>(pctx, woT, bo, x, px1, D_, D_, 1.0f);

    // 7. h2 = round(LN2(x1))
    ln_kernel<<<M_, 256>>>(px1, ln2_g, ln2_b, ph2);

    // 8. ff = round(relu(h2 @ W1 + b1))
    dim3 gF(F_ / TN, M_ / TM);
    gemm_mma<1><<<gF, 256, GEMM_SMEM>>>(ph2, w1T, b1, nullptr, pff, F_, D_, 1.0f);

    // 9. out = x1 + ff @ W2 + b2
    gemm_mma<2><<<gD, 256, GEMM_SMEM>>>(pff, w2T, b2, px1, out, D_, F_, 1.0f);
}

// round 9
// speedup vs baseline: 3.4602x; 1.1083x over previous
#include <cuda_runtime.h>
#include <cstdint>
#include <math.h>

#define S_  2048
#define B_  4
#define D_  1024
#define H_  16
#define DH_ 64
#define F_  4096
#define M_  8192   // S_*B_
#define QKVS 3072  // fused qkv row stride

// ---------------- scratch (device globals; no allocation allowed) ------------
__device__ float g_h   [M_ * D_];
__device__ float g_qkv [(size_t)M_ * QKVS];
__device__ float g_ctx [M_ * D_];
__device__ float g_x1  [M_ * D_];
__device__ float g_h2  [M_ * D_];
__device__ float g_ff  [(size_t)M_ * F_];
// transposed (+tf32-rounded) weights, [N, K] K-major
__device__ float g_wqkvT[(size_t)QKVS * D_];  // rows: 0-1023 Wq(*0.125), 1024-2047 Wk, 2048-3071 Wv
__device__ float g_bqkv [QKVS];
__device__ float g_woT[D_ * D_];
__device__ float g_w1T[(size_t)F_ * D_];   // [4096,1024]
__device__ float g_w2T[(size_t)D_ * F_];   // [1024,4096]

// ---------------- helpers -----------------------------------------------------
__device__ __forceinline__ uint32_t smem_u32(const void* p) {
    uint32_t a;
    asm("{ .reg .u64 t; cvta.to.shared.u64 t, %1; cvt.u32.u64 %0, t; }" : "=r"(a) : "l"(p));
    return a;
}
__device__ __forceinline__ float tf32rn(float x) {
    float r;
    asm("cvt.rna.tf32.f32 %0, %1;" : "=f"(r) : "f"(x));
    return r;
}
#define CP_ASYNC16(dst, src) \
    asm volatile("cp.async.cg.shared.global [%0], [%1], 16;" :: "r"(dst), "l"(src))
#define CP_COMMIT() asm volatile("cp.async.commit_group;" ::: "memory")

__device__ __forceinline__ void mma_tf32(float* c, const uint32_t* a, const uint32_t* b) {
    asm volatile(
        "mma.sync.aligned.m16n8k8.row.col.f32.tf32.tf32.f32 "
        "{%0,%1,%2,%3}, {%4,%5,%6,%7}, {%8,%9}, {%0,%1,%2,%3};"
        : "+f"(c[0]), "+f"(c[1]), "+f"(c[2]), "+f"(c[3])
        : "r"(a[0]), "r"(a[1]), "r"(a[2]), "r"(a[3]), "r"(b[0]), "r"(b[1]));
}

// ---------------- tf32 mma.sync GEMM ------------------------------------------
// C[M,N] = A[M,K] @ Bt[N,K]^T (+epilogue)
// 128x128 tile, 256 thr (8 warps 2x4, warp tile 64x32), K-chunk 32,
// 2-stage double buffer, 2 CTAs/SM.
#define TM    128
#define TN    128
#define TK    32
#define NSTG  2
#define LDSD  36
#define TILEF (128 * LDSD)
#define GEMM_SMEM (NSTG * 2 * TILEF * 4)   // 73728 bytes

// EPI: 0 +bias | 1 round(relu(+bias)) | 2 +bias+residual | 3 round(+bias)
template<int EPI>
__global__ void __launch_bounds__(256, 2)
gemm_mma(const float* __restrict__ A, const float* __restrict__ Bt,
         const float* __restrict__ bias, const float* __restrict__ res,
         float* __restrict__ C, int N, int K) {
    extern __shared__ float sm[];
    float* As = sm;
    float* Bs = sm + NSTG * TILEF;

    const int tid  = threadIdx.x;
    const int lane = tid & 31, wid = tid >> 5;
    const int wm = wid & 1, wn = wid >> 1;
    const int m0 = blockIdx.y * TM, n0 = blockIdx.x * TN;
    const int g = lane >> 2, t = lane & 3;
    const int CH = K / TK;

    float c[4][4][4];
    #pragma unroll
    for (int i = 0; i < 4; i++)
        #pragma unroll
        for (int j = 0; j < 4; j++)
            #pragma unroll
            for (int r = 0; r < 4; r++) c[i][j][r] = 0.f;

    auto load_stage = [&](int cc, int s) {
        const float* Ab = A  + (size_t)m0 * K + cc * TK;
        const float* Bb = Bt + (size_t)n0 * K + cc * TK;
        float* as = As + s * TILEF;
        float* bs = Bs + s * TILEF;
        #pragma unroll
        for (int i = 0; i < 4; i++) {
            int gi = tid + 256 * i;
            int r = gi >> 3, gc = gi & 7;
            CP_ASYNC16(smem_u32(as + r * LDSD + gc * 4), Ab + (size_t)r * K + gc * 4);
            CP_ASYNC16(smem_u32(bs + r * LDSD + gc * 4), Bb + (size_t)r * K + gc * 4);
        }
        CP_COMMIT();
    };

    load_stage(0, 0);

    for (int cc = 0; cc < CH; cc++) {
        asm volatile("cp.async.wait_group 0;" ::: "memory");
        __syncthreads();

        if (cc + 1 < CH) load_stage(cc + 1, (cc + 1) & 1);

        const float* as = As + (cc & 1) * TILEF + (wm * 64) * LDSD;
        const float* bs = Bs + (cc & 1) * TILEF + (wn * 32) * LDSD;

        #pragma unroll
        for (int s = 0; s < 4; s++) {
            const int k0 = s * 8;
            uint32_t af[4][4], bf[4][2];
            #pragma unroll
            for (int i = 0; i < 4; i++) {
                const uint32_t* ap = (const uint32_t*)(as + (i * 16 + g) * LDSD + k0 + t);
                af[i][0] = ap[0];
                af[i][1] = ap[8 * LDSD];
                af[i][2] = ap[4];
                af[i][3] = ap[8 * LDSD + 4];
            }
            #pragma unroll
            for (int j = 0; j < 4; j++) {
                const uint32_t* bp = (const uint32_t*)(bs + (j * 8 + g) * LDSD + k0 + t);
                bf[j][0] = bp[0];
                bf[j][1] = bp[4];
            }
            #pragma unroll
            for (int i = 0; i < 4; i++)
                #pragma unroll
                for (int j = 0; j < 4; j++)
                    mma_tf32(c[i][j], af[i], bf[j]);
        }
        __syncthreads();
    }

    #pragma unroll
    for (int i = 0; i < 4; i++) {
        const int r0 = m0 + wm * 64 + i * 16 + g;
        #pragma unroll
        for (int j = 0; j < 4; j++) {
            const int col = n0 + wn * 32 + j * 8 + 2 * t;
            float b0 = bias[col], b1 = bias[col + 1];
            float v0 = c[i][j][0] + b0, v1 = c[i][j][1] + b1;
            float v2 = c[i][j][2] + b0, v3 = c[i][j][3] + b1;
            if (EPI == 1) {
                v0 = tf32rn(fmaxf(v0, 0.f)); v1 = tf32rn(fmaxf(v1, 0.f));
                v2 = tf32rn(fmaxf(v2, 0.f)); v3 = tf32rn(fmaxf(v3, 0.f));
            }
            if (EPI == 2) {
                float2 ra = *(const float2*)(res + (size_t)r0 * N + col);
                float2 rb = *(const float2*)(res + (size_t)(r0 + 8) * N + col);
                v0 += ra.x; v1 += ra.y; v2 += rb.x; v3 += rb.y;
            }
            if (EPI == 3) {
                v0 = tf32rn(v0); v1 = tf32rn(v1);
                v2 = tf32rn(v2); v3 = tf32rn(v3);
            }
            *(float2*)(C + (size_t)r0 * N + col)       = make_float2(v0, v1);
            *(float2*)(C + (size_t)(r0 + 8) * N + col) = make_float2(v2, v3);
        }
    }
}

// ---------------- weight transpose + tf32-RN round (+scale fold) --------------
__global__ void transpose_round(const float* __restrict__ in, float* __restrict__ out,
                                int K, int N, float scale) {
    __shared__ float t[32][33];
    int n0 = blockIdx.x * 32, k0 = blockIdx.y * 32;
    #pragma unroll
    for (int i = threadIdx.y; i < 32; i += 8)
        t[i][threadIdx.x] = in[(size_t)(k0 + i) * N + n0 + threadIdx.x];
    __syncthreads();
    #pragma unroll
    for (int i = threadIdx.y; i < 32; i += 8)
        out[(size_t)(n0 + i) * K + k0 + threadIdx.x] = tf32rn(t[threadIdx.x][i] * scale);
}

__global__ void concat_bias(const float* __restrict__ bq, const float* __restrict__ bk,
                            const float* __restrict__ bv, float* __restrict__ out) {
    int i = blockIdx.x * 256 + threadIdx.x;   // 0..3071
    float v = (i < 1024) ? bq[i] * 0.125f : (i < 2048) ? bk[i - 1024] : bv[i - 2048];
    out[i] = v;
}

// ---------------- block reduction --------------------------------------------
__device__ __forceinline__ float blockReduceSum256(float val) {
    __shared__ float sh[8];
    #pragma unroll
    for (int o = 16; o; o >>= 1) val += __shfl_xor_sync(0xffffffffu, val, o);
    int w = threadIdx.x >> 5;
    if ((threadIdx.x & 31) == 0) sh[w] = val;
    __syncthreads();
    float tot = 0.f;
    #pragma unroll
    for (int i = 0; i < 8; i++) tot += sh[i];
    __syncthreads();
    return tot;
}

// ---------------- LayerNorm (output rounded to tf32 — feeds GEMMs only) ------
__global__ void ln_kernel(const float* __restrict__ x,
                          const float* __restrict__ g,
                          const float* __restrict__ b,
                          float* __restrict__ out) {
    int row = blockIdx.x;
    const float4* xr = (const float4*)(x + (size_t)row * D_);
    float4 xv = xr[threadIdx.x];

    float s = xv.x + xv.y + xv.z + xv.w;
    float mean = blockReduceSum256(s) * (1.0f / D_);

    float dx0 = xv.x - mean, dx1 = xv.y - mean, dx2 = xv.z - mean, dx3 = xv.w - mean;
    float s2 = dx0*dx0 + dx1*dx1 + dx2*dx2 + dx3*dx3;
    float var = blockReduceSum256(s2) * (1.0f / D_);
    float inv = rsqrtf(var + 1e-5f);

    float4 gv = ((const float4*)g)[threadIdx.x];
    float4 bv = ((const float4*)b)[threadIdx.x];
    float4 o;
    o.x = tf32rn(dx0 * inv * gv.x + bv.x);
    o.y = tf32rn(dx1 * inv * gv.y + bv.y);
    o.z = tf32rn(dx2 * inv * gv.z + bv.z);
    o.w = tf32rn(dx3 * inv * gv.w + bv.w);
    ((float4*)(out + (size_t)row * D_))[threadIdx.x] = o;
}

// ---------------- Flash attention with tf32 mma.sync ---------------------------
// grid (S/128, B*H), 256 thr (8 warps x 16 Q rows). q/k/v in fused buffer, stride QKVS.
#define AST 68
#define NKT (S_ / 64)
#define ATT_SMEM (5 * 128 * AST * 4)   // 174080

__global__ void __launch_bounds__(256, 1)
attn_mma(const float* __restrict__ qkv, float* __restrict__ ctx) {
    extern __shared__ float sm[];
    float* Qs = sm;                    // [128][AST]
    float* Ps = sm + 128 * AST;        // [128][AST]
    float* KV = sm + 256 * AST;        // 3 x [128][AST]

    const int tid = threadIdx.x;
    const int lane = tid & 31, wid = tid >> 5;
    const int g = lane >> 2, t = lane & 3;
    const int bh = blockIdx.y, b = bh >> 4, h = bh & 15;
    const int qt = blockIdx.x;
    const int colbase = h * 64;
    const float* q = qkv;
    const float* k = qkv + 1024;
    const float* v = qkv + 2048;

    auto issue_kv = [&](int kt) {
        float* st = KV + (kt % 3) * 128 * AST;
        #pragma unroll
        for (int j = 0; j < 8; j++) {
            int gi = tid + 256 * j;          // 0..2047
            int r = (gi & 1023) >> 4, c4 = (gi & 15) << 2;
            const float* src = (gi < 1024)
                ? k + ((size_t)(kt * 64 + r) * B_ + b) * QKVS + colbase + c4
                : v + ((size_t)(kt * 64 + r) * B_ + b) * QKVS + colbase + c4;
            float* dst = st + ((gi < 1024) ? r : (64 + r)) * AST + c4;
            CP_ASYNC16(smem_u32(dst), src);
        }
        CP_COMMIT();
    };
    issue_kv(0);
    issue_kv(1);

    // load Q tile (pre-scaled + tf32-rounded by fused GEMM)
    for (int i = tid; i < 128 * 16; i += 256) {
        int r = i >> 4, c4 = (i & 15) << 2;
        *(float4*)(Qs + r * AST + c4) =
            *(const float4*)(q + ((size_t)(qt * 128 + r) * B_ + b) * QKVS + colbase + c4);
    }
    __syncthreads();

    uint32_t qf[8][4];
    {
        const uint32_t* q0 = (const uint32_t*)(Qs + (wid * 16 + g) * AST);
        const uint32_t* q1 = (const uint32_t*)(Qs + (wid * 16 + g + 8) * AST);
        #pragma unroll
        for (int kc = 0; kc < 8; kc++) {
            qf[kc][0] = q0[kc * 8 + t];
            qf[kc][1] = q1[kc * 8 + t];
            qf[kc][2] = q0[kc * 8 + t + 4];
            qf[kc][3] = q1[kc * 8 + t + 4];
        }
    }

    float mr[2] = {-1e30f, -1e30f}, lr[2] = {0.f, 0.f};
    float O[8][4];
    #pragma unroll
    for (int nt = 0; nt < 8; nt++)
        #pragma unroll
        for (int r = 0; r < 4; r++) O[nt][r] = 0.f;

    float* Pw0 = Ps + (wid * 16 + g) * AST;
    float* Pw1 = Ps + (wid * 16 + g + 8) * AST;

    for (int kt = 0; kt < NKT; kt++) {
        if (kt == NKT - 1) asm volatile("cp.async.wait_group 0;" ::: "memory");
        else               asm volatile("cp.async.wait_group 1;" ::: "memory");
        __syncthreads();
        if (kt + 2 < NKT) issue_kv(kt + 2);

        const float* Ks = KV + (kt % 3) * 128 * AST;
        const float* Vs = Ks + 64 * AST;

        float s[8][4];
        #pragma unroll
        for (int nt = 0; nt < 8; nt++)
            #pragma unroll
            for (int r = 0; r < 4; r++) s[nt][r] = 0.f;

        #pragma unroll
        for (int kc = 0; kc < 8; kc++) {
            #pragma unroll
            for (int nt = 0; nt < 8; nt++) {
                const uint32_t* kp = (const uint32_t*)(Ks + (nt * 8 + g) * AST + kc * 8 + t);
                uint32_t bf[2] = { kp[0], kp[4] };
                mma_tf32(s[nt], qf[kc], bf);
            }
        }

        #pragma unroll
        for (int ro = 0; ro < 2; ro++) {
            float tmax = -1e30f;
            #pragma unroll
            for (int nt = 0; nt < 8; nt++)
                tmax = fmaxf(tmax, fmaxf(s[nt][2 * ro], s[nt][2 * ro + 1]));
            tmax = fmaxf(tmax, __shfl_xor_sync(0xffffffffu, tmax, 1));
            tmax = fmaxf(tmax, __shfl_xor_sync(0xffffffffu, tmax, 2));
            float newm = fmaxf(mr[ro], tmax);
            float corr = __expf(mr[ro] - newm);
            mr[ro] = newm;
            float sum = 0.f;
            float* Pw = ro ? Pw1 : Pw0;
            #pragma unroll
            for (int nt = 0; nt < 8; nt++) {
                float p0 = __expf(s[nt][2 * ro]     - newm);
                float p1 = __expf(s[nt][2 * ro + 1] - newm);
                sum += p0 + p1;
                *(float2*)(Pw + nt * 8 + 2 * t) = make_float2(tf32rn(p0), tf32rn(p1));
                O[nt][2 * ro]     *= corr;
                O[nt][2 * ro + 1] *= corr;
            }
            sum += __shfl_xor_sync(0xffffffffu, sum, 1);
            sum += __shfl_xor_sync(0xffffffffu, sum, 2);
            lr[ro] = lr[ro] * corr + sum;
        }
        __syncwarp();

        #pragma unroll
        for (int kc = 0; kc < 8; kc++) {
            uint32_t pa[4];
            pa[0] = ((const uint32_t*)Pw0)[kc * 8 + t];
            pa[1] = ((const uint32_t*)Pw1)[kc * 8 + t];
            pa[2] = ((const uint32_t*)Pw0)[kc * 8 + t + 4];
            pa[3] = ((const uint32_t*)Pw1)[kc * 8 + t + 4];
            #pragma unroll
            for (int nt = 0; nt < 8; nt++) {
                uint32_t bf[2];
                bf[0] = *(const uint32_t*)(Vs + (kc * 8 + t) * AST + nt * 8 + g);
                bf[1] = *(const uint32_t*)(Vs + (kc * 8 + t + 4) * AST + nt * 8 + g);
                mma_tf32(O[nt], pa, bf);
            }
        }
        __syncwarp();
    }

    float inv0 = 1.f / lr[0], inv1 = 1.f / lr[1];
    const int r0 = qt * 128 + wid * 16 + g;
    #pragma unroll
    for (int nt = 0; nt < 8; nt++) {
        int col = colbase + nt * 8 + 2 * t;
        *(float2*)(ctx + ((size_t)r0 * B_ + b) * D_ + col) =
            make_float2(tf32rn(O[nt][0] * inv0), tf32rn(O[nt][1] * inv0));
        *(float2*)(ctx + ((size_t)(r0 + 8) * B_ + b) * D_ + col) =
            make_float2(tf32rn(O[nt][2] * inv1), tf32rn(O[nt][3] * inv1));
    }
}

// ---------------- launch ------------------------------------------------------
extern "C" void kernel_launch(void* const* d_in, const int* in_sizes, int n_in,
                              void* d_out, int out_size) {
    const float* x     = (const float*)d_in[0];
    const float* ln1_g = (const float*)d_in[1];
    const float* ln1_b = (const float*)d_in[2];
    const float* ln2_g = (const float*)d_in[3];
    const float* ln2_b = (const float*)d_in[4];
    const float* Wq    = (const float*)d_in[5];
    const float* bq    = (const float*)d_in[6];
    const float* Wk    = (const float*)d_in[7];
    const float* bk    = (const float*)d_in[8];
    const float* Wv    = (const float*)d_in[9];
    const float* bv    = (const float*)d_in[10];
    const float* Wo    = (const float*)d_in[11];
    const float* bo    = (const float*)d_in[12];
    const float* W1    = (const float*)d_in[13];
    const float* b1    = (const float*)d_in[14];
    const float* W2    = (const float*)d_in[15];
    const float* b2    = (const float*)d_in[16];
    float* out = (float*)d_out;

    float *ph, *pqkv, *pctx, *px1, *ph2, *pff;
    float *wqkvT, *bqkv, *woT, *w1T, *w2T;
    cudaGetSymbolAddress((void**)&ph,   g_h);
    cudaGetSymbolAddress((void**)&pqkv, g_qkv);
    cudaGetSymbolAddress((void**)&pctx, g_ctx);
    cudaGetSymbolAddress((void**)&px1,  g_x1);
    cudaGetSymbolAddress((void**)&ph2,  g_h2);
    cudaGetSymbolAddress((void**)&pff,  g_ff);
    cudaGetSymbolAddress((void**)&wqkvT,g_wqkvT);
    cudaGetSymbolAddress((void**)&bqkv, g_bqkv);
    cudaGetSymbolAddress((void**)&woT,  g_woT);
    cudaGetSymbolAddress((void**)&w1T,  g_w1T);
    cudaGetSymbolAddress((void**)&w2T,  g_w2T);

    cudaFuncSetAttribute(attn_mma,    cudaFuncAttributeMaxDynamicSharedMemorySize, ATT_SMEM);
    cudaFuncSetAttribute(gemm_mma<1>, cudaFuncAttributeMaxDynamicSharedMemorySize, GEMM_SMEM);
    cudaFuncSetAttribute(gemm_mma<2>, cudaFuncAttributeMaxDynamicSharedMemorySize, GEMM_SMEM);
    cudaFuncSetAttribute(gemm_mma<3>, cudaFuncAttributeMaxDynamicSharedMemorySize, GEMM_SMEM);

    // 0. transpose + round weights to [N,K]; Wq scaled by 1/sqrt(DH) (exact pow2)
    dim3 tb(32, 8);
    transpose_round<<<dim3(D_/32, D_/32), tb>>>(Wq, wqkvT,            D_, D_, 0.125f);
    transpose_round<<<dim3(D_/32, D_/32), tb>>>(Wk, wqkvT + 1024*D_,  D_, D_, 1.0f);
    transpose_round<<<dim3(D_/32, D_/32), tb>>>(Wv, wqkvT + 2048*D_,  D_, D_, 1.0f);
    transpose_round<<<dim3(D_/32, D_/32), tb>>>(Wo, woT, D_, D_, 1.0f);
    transpose_round<<<dim3(F_/32, D_/32), tb>>>(W1, w1T, D_, F_, 1.0f);
    transpose_round<<<dim3(D_/32, F_/32), tb>>>(W2, w2T, F_, D_, 1.0f);
    concat_bias<<<QKVS/256, 256>>>(bq, bk, bv, bqkv);

    // 1. h = round(LN1(x))
    ln_kernel<<<M_, 256>>>(x, ln1_g, ln1_b, ph);

    // 2. fused qkv = round(h @ [Wq*s|Wk|Wv] + [bq*s|bk|bv])
    gemm_mma<3><<<dim3(QKVS / TN, M_ / TM), 256, GEMM_SMEM>>>(ph, wqkvT, bqkv, nullptr, pqkv, QKVS, D_);

    // 3. flash attention (tf32 mma) -> ctx (rounded)
    attn_mma<<<dim3(S_ / 128, B_ * H_), 256, ATT_SMEM>>>(pqkv, pctx);

    // 4. x1 = x + ctx @ Wo + bo
    dim3 gD(D_ / TN, M_ / TM);
    gemm_mma<2><<<gD, 256, GEMM_SMEM>>>(pctx, woT, bo, x, px1, D_, D_);

    // 5. h2 = round(LN2(x1))
    ln_kernel<<<M_, 256>>>(px1, ln2_g, ln2_b, ph2);

    // 6. ff = round(relu(h2 @ W1 + b1))
    gemm_mma<1><<<dim3(F_ / TN, M_ / TM), 256, GEMM_SMEM>>>(ph2, w1T, b1, nullptr, pff, F_, D_);

    // 7. out = x1 + ff @ W2 + b2
    gemm_mma<2><<<gD, 256, GEMM_SMEM>>>(pff, w2T, b2, px1, out, D_, F_);
}

// round 11
// speedup vs baseline: 6.1375x; 1.7738x over previous
#include <cuda_runtime.h>
#include <cuda_fp16.h>
#include <cstdint>
#include <math.h>

#define S_  2048
#define B_  4
#define D_  1024
#define H_  16
#define DH_ 64
#define F_  4096
#define M_  8192   // S_*B_
#define QKVS 3072  // fused qkv row stride

// ---------------- scratch (device globals; no allocation allowed) ------------
__device__ __half g_h   [M_ * D_];
__device__ __half g_qkv [(size_t)M_ * QKVS];
__device__ __half g_ctx [M_ * D_];
__device__ float  g_x1  [M_ * D_];
__device__ __half g_h2  [M_ * D_];
__device__ __half g_ff  [(size_t)M_ * F_];
// transposed (half) weights, [N, K] K-major
__device__ __half g_wqkvT[(size_t)QKVS * D_];  // rows: 0-1023 Wq*0.125, 1024-2047 Wk, 2048-3071 Wv
__device__ float  g_bqkv [QKVS];
__device__ __half g_woT[D_ * D_];
__device__ __half g_w1T[(size_t)F_ * D_];   // [4096,1024]
__device__ __half g_w2T[(size_t)D_ * F_];   // [1024,4096]

// ---------------- helpers -----------------------------------------------------
__device__ __forceinline__ uint32_t smem_u32(const void* p) {
    uint32_t a;
    asm("{ .reg .u64 t; cvta.to.shared.u64 t, %1; cvt.u32.u64 %0, t; }" : "=r"(a) : "l"(p));
    return a;
}
#define CP_ASYNC16(dst, src) \
    asm volatile("cp.async.cg.shared.global [%0], [%1], 16;" :: "r"(dst), "l"(src))
#define CP_COMMIT() asm volatile("cp.async.commit_group;" ::: "memory")

__device__ __forceinline__ void mma_f16(float* c, const uint32_t* a, const uint32_t* b) {
    asm volatile(
        "mma.sync.aligned.m16n8k16.row.col.f32.f16.f16.f32 "
        "{%0,%1,%2,%3}, {%4,%5,%6,%7}, {%8,%9}, {%0,%1,%2,%3};"
        : "+f"(c[0]), "+f"(c[1]), "+f"(c[2]), "+f"(c[3])
        : "r"(a[0]), "r"(a[1]), "r"(a[2]), "r"(a[3]), "r"(b[0]), "r"(b[1]));
}
__device__ __forceinline__ void ldmatrix_x2_trans(uint32_t& r0, uint32_t& r1, uint32_t addr) {
    asm volatile("ldmatrix.sync.aligned.m8n8.x2.trans.shared.b16 {%0,%1}, [%2];"
                 : "=r"(r0), "=r"(r1) : "r"(addr));
}
__device__ __forceinline__ uint32_t h2_bits(__half2 h) {
    uint32_t u;
    *(__half2*)&u = h;
    return u;
}

// ---------------- fp16 mma.sync GEMM ------------------------------------------
// C[M,N] = A[M,K] @ Bt[N,K]^T (+epilogue). A,Bt half; accum fp32.
// 128x128 tile, 256 thr (8 warps 2x4, warp tile 64x32), K-chunk 32 halfs,
// 3-stage cp.async, 2 CTAs/SM.
#define TM    128
#define TN    128
#define TK    32
#define NSTG  3
#define LDH   40                       // smem row stride in halfs
#define TILEH (128 * LDH)
#define GEMM_SMEM (NSTG * 2 * TILEH * 2)   // 61440 bytes

// EPI: 1 half(relu(+bias)) | 2 +bias+residual (float out) | 3 half(+bias)
template<int EPI, typename OutT>
__global__ void __launch_bounds__(256, 2)
gemm_mma(const __half* __restrict__ A, const __half* __restrict__ Bt,
         const float* __restrict__ bias, const float* __restrict__ res,
         OutT* __restrict__ C, int N, int K) {
    extern __shared__ __half smh[];
    __half* As = smh;
    __half* Bs = smh + NSTG * TILEH;

    const int tid  = threadIdx.x;
    const int lane = tid & 31, wid = tid >> 5;
    const int wm = wid & 1, wn = wid >> 1;
    const int m0 = blockIdx.y * TM, n0 = blockIdx.x * TN;
    const int g = lane >> 2, t = lane & 3;
    const int CH = K / TK;

    float c[4][4][4];
    #pragma unroll
    for (int i = 0; i < 4; i++)
        #pragma unroll
        for (int j = 0; j < 4; j++)
            #pragma unroll
            for (int r = 0; r < 4; r++) c[i][j][r] = 0.f;

    auto load_stage = [&](int cc, int s) {
        const __half* Ab = A  + (size_t)m0 * K + cc * TK;
        const __half* Bb = Bt + (size_t)n0 * K + cc * TK;
        __half* as = As + s * TILEH;
        __half* bs = Bs + s * TILEH;
        #pragma unroll
        for (int i = 0; i < 4; i++) {
            int gi = tid + 256 * i;           // 0..1023
            int mat = gi >> 9;                // 0:A 1:B
            int o = gi & 511;
            int r = o >> 2, gc = o & 3;
            if (mat == 0)
                CP_ASYNC16(smem_u32(as + r * LDH + gc * 8), Ab + (size_t)r * K + gc * 8);
            else
                CP_ASYNC16(smem_u32(bs + r * LDH + gc * 8), Bb + (size_t)r * K + gc * 8);
        }
        CP_COMMIT();
    };

    load_stage(0, 0);
    load_stage(1, 1);

    for (int cc = 0; cc < CH; cc++) {
        if (cc == CH - 1) asm volatile("cp.async.wait_group 0;" ::: "memory");
        else              asm volatile("cp.async.wait_group 1;" ::: "memory");
        __syncthreads();

        if (cc + 2 < CH) load_stage(cc + 2, (cc + 2) % NSTG);

        const __half* as = As + (cc % NSTG) * TILEH + (wm * 64) * LDH;
        const __half* bs = Bs + (cc % NSTG) * TILEH + (wn * 32) * LDH;

        #pragma unroll
        for (int kc = 0; kc < 2; kc++) {           // 2 k-steps of 16 halfs
            uint32_t af[4][4], bf[4][2];
            #pragma unroll
            for (int i = 0; i < 4; i++) {
                const uint32_t* ap = (const uint32_t*)(as + (i * 16 + g) * LDH) + kc * 8 + t;
                af[i][0] = ap[0];
                af[i][1] = ap[8 * (LDH / 2)];
                af[i][2] = ap[4];
                af[i][3] = ap[8 * (LDH / 2) + 4];
            }
            #pragma unroll
            for (int j = 0; j < 4; j++) {
                const uint32_t* bp = (const uint32_t*)(bs + (j * 8 + g) * LDH) + kc * 8 + t;
                bf[j][0] = bp[0];
                bf[j][1] = bp[4];
            }
            #pragma unroll
            for (int i = 0; i < 4; i++)
                #pragma unroll
                for (int j = 0; j < 4; j++)
                    mma_f16(c[i][j], af[i], bf[j]);
        }
        __syncthreads();
    }

    #pragma unroll
    for (int i = 0; i < 4; i++) {
        const int r0 = m0 + wm * 64 + i * 16 + g;
        #pragma unroll
        for (int j = 0; j < 4; j++) {
            const int col = n0 + wn * 32 + j * 8 + 2 * t;
            float b0 = bias[col], b1 = bias[col + 1];
            float v0 = c[i][j][0] + b0, v1 = c[i][j][1] + b1;
            float v2 = c[i][j][2] + b0, v3 = c[i][j][3] + b1;
            if (EPI == 1) {
                v0 = fmaxf(v0, 0.f); v1 = fmaxf(v1, 0.f);
                v2 = fmaxf(v2, 0.f); v3 = fmaxf(v3, 0.f);
            }
            if (EPI == 2) {
                float2 ra = *(const float2*)(res + (size_t)r0 * N + col);
                float2 rb = *(const float2*)(res + (size_t)(r0 + 8) * N + col);
                v0 += ra.x; v1 += ra.y; v2 += rb.x; v3 += rb.y;
                *(float2*)((float*)C + (size_t)r0 * N + col)       = make_float2(v0, v1);
                *(float2*)((float*)C + (size_t)(r0 + 8) * N + col) = make_float2(v2, v3);
            } else {
                *(__half2*)((__half*)C + (size_t)r0 * N + col) =
                    __floats2half2_rn(v0, v1);
                *(__half2*)((__half*)C + (size_t)(r0 + 8) * N + col) =
                    __floats2half2_rn(v2, v3);
            }
        }
    }
}

// ---------------- weight transpose -> half (+scale fold) ----------------------
__global__ void transpose_half(const float* __restrict__ in, __half* __restrict__ out,
                               int K, int N, float scale) {
    __shared__ float t[32][33];
    int n0 = blockIdx.x * 32, k0 = blockIdx.y * 32;
    #pragma unroll
    for (int i = threadIdx.y; i < 32; i += 8)
        t[i][threadIdx.x] = in[(size_t)(k0 + i) * N + n0 + threadIdx.x];
    __syncthreads();
    #pragma unroll
    for (int i = threadIdx.y; i < 32; i += 8)
        out[(size_t)(n0 + i) * K + k0 + threadIdx.x] = __float2half_rn(t[threadIdx.x][i] * scale);
}

__global__ void concat_bias(const float* __restrict__ bq, const float* __restrict__ bk,
                            const float* __restrict__ bv, float* __restrict__ out) {
    int i = blockIdx.x * 256 + threadIdx.x;
    float v = (i < 1024) ? bq[i] * 0.125f : (i < 2048) ? bk[i - 1024] : bv[i - 2048];
    out[i] = v;
}

// ---------------- block reduction --------------------------------------------
__device__ __forceinline__ float blockReduceSum256(float val) {
    __shared__ float sh[8];
    #pragma unroll
    for (int o = 16; o; o >>= 1) val += __shfl_xor_sync(0xffffffffu, val, o);
    int w = threadIdx.x >> 5;
    if ((threadIdx.x & 31) == 0) sh[w] = val;
    __syncthreads();
    float tot = 0.f;
    #pragma unroll
    for (int i = 0; i < 8; i++) tot += sh[i];
    __syncthreads();
    return tot;
}

// ---------------- LayerNorm: f32 in -> half out -------------------------------
__global__ void ln_kernel(const float* __restrict__ x,
                          const float* __restrict__ g,
                          const float* __restrict__ b,
                          __half* __restrict__ out) {
    int row = blockIdx.x;
    const float4* xr = (const float4*)(x + (size_t)row * D_);
    float4 xv = xr[threadIdx.x];

    float s = xv.x + xv.y + xv.z + xv.w;
    float mean = blockReduceSum256(s) * (1.0f / D_);

    float dx0 = xv.x - mean, dx1 = xv.y - mean, dx2 = xv.z - mean, dx3 = xv.w - mean;
    float s2 = dx0*dx0 + dx1*dx1 + dx2*dx2 + dx3*dx3;
    float var = blockReduceSum256(s2) * (1.0f / D_);
    float inv = rsqrtf(var + 1e-5f);

    float4 gv = ((const float4*)g)[threadIdx.x];
    float4 bv = ((const float4*)b)[threadIdx.x];
    __half2 h0 = __floats2half2_rn(dx0 * inv * gv.x + bv.x, dx1 * inv * gv.y + bv.y);
    __half2 h1 = __floats2half2_rn(dx2 * inv * gv.z + bv.z, dx3 * inv * gv.w + bv.w);
    uint2 pk = make_uint2(h2_bits(h0), h2_bits(h1));
    *(uint2*)(out + (size_t)row * D_ + 4 * threadIdx.x) = pk;
}

// ---------------- Flash attention, fp16 mma.sync -------------------------------
// grid (S/128, B*H), 256 thr (8 warps x 16 Q rows). q/k/v half, fused buffer.
#define ASTH 72                         // smem row stride (halfs)
#define NKT (S_ / 64)
#define ATT_SMEM (5 * 128 * ASTH * 2)   // 92160 bytes

__global__ void __launch_bounds__(256, 1)
attn_mma(const __half* __restrict__ qkv, __half* __restrict__ ctx) {
    extern __shared__ __half smh[];
    __half* Qs = smh;                    // [128][ASTH]
    __half* Ps = smh + 128 * ASTH;       // [128][ASTH]
    __half* KV = smh + 256 * ASTH;       // 3 x [128][ASTH]: rows 0-63 K, 64-127 V

    const int tid = threadIdx.x;
    const int lane = tid & 31, wid = tid >> 5;
    const int g = lane >> 2, t = lane & 3;
    const int bh = blockIdx.y, b = bh >> 4, h = bh & 15;
    const int qt = blockIdx.x;
    const int colbase = h * 64;
    const __half* q = qkv;
    const __half* k = qkv + 1024;
    const __half* v = qkv + 2048;

    auto issue_kv = [&](int kt) {
        __half* st = KV + (kt % 3) * 128 * ASTH;
        #pragma unroll
        for (int j = 0; j < 4; j++) {
            int gi = tid + 256 * j;          // 0..1023
            int r = (gi & 511) >> 3, c8 = (gi & 7) << 3;
            const __half* src = (gi < 512)
                ? k + ((size_t)(kt * 64 + r) * B_ + b) * QKVS + colbase + c8
                : v + ((size_t)(kt * 64 + r) * B_ + b) * QKVS + colbase + c8;
            __half* dst = st + ((gi < 512) ? r : (64 + r)) * ASTH + c8;
            CP_ASYNC16(smem_u32(dst), src);
        }
        CP_COMMIT();
    };
    issue_kv(0);
    issue_kv(1);

    // load Q tile
    for (int i = tid; i < 128 * 8; i += 256) {
        int r = i >> 3, c8 = (i & 7) << 3;
        *(uint4*)(Qs + r * ASTH + c8) =
            *(const uint4*)(q + ((size_t)(qt * 128 + r) * B_ + b) * QKVS + colbase + c8);
    }
    __syncthreads();

    // Q fragments: 4 k-steps of 16 (DH=64)
    uint32_t qf[4][4];
    {
        const uint32_t* q0 = (const uint32_t*)(Qs + (wid * 16 + g) * ASTH);
        const uint32_t* q1 = (const uint32_t*)(Qs + (wid * 16 + g + 8) * ASTH);
        #pragma unroll
        for (int kc = 0; kc < 4; kc++) {
            qf[kc][0] = q0[kc * 8 + t];
            qf[kc][1] = q1[kc * 8 + t];
            qf[kc][2] = q0[kc * 8 + t + 4];
            qf[kc][3] = q1[kc * 8 + t + 4];
        }
    }

    float mr[2] = {-1e30f, -1e30f}, lr[2] = {0.f, 0.f};
    float O[8][4];
    #pragma unroll
    for (int nt = 0; nt < 8; nt++)
        #pragma unroll
        for (int r = 0; r < 4; r++) O[nt][r] = 0.f;

    __half* Pw0 = Ps + (wid * 16 + g) * ASTH;
    __half* Pw1 = Ps + (wid * 16 + g + 8) * ASTH;

    for (int kt = 0; kt < NKT; kt++) {
        if (kt == NKT - 1) asm volatile("cp.async.wait_group 0;" ::: "memory");
        else               asm volatile("cp.async.wait_group 1;" ::: "memory");
        __syncthreads();
        if (kt + 2 < NKT) issue_kv(kt + 2);

        const __half* Ks = KV + (kt % 3) * 128 * ASTH;
        const __half* Vs = Ks + 64 * ASTH;

        // S = Q @ K^T
        float s[8][4];
        #pragma unroll
        for (int nt = 0; nt < 8; nt++)
            #pragma unroll
            for (int r = 0; r < 4; r++) s[nt][r] = 0.f;

        #pragma unroll
        for (int kc = 0; kc < 4; kc++) {
            #pragma unroll
            for (int nt = 0; nt < 8; nt++) {
                const uint32_t* kp = (const uint32_t*)(Ks + (nt * 8 + g) * ASTH) + kc * 8 + t;
                uint32_t bf[2] = { kp[0], kp[4] };
                mma_f16(s[nt], qf[kc], bf);
            }
        }

        // online softmax (rows g and g+8)
        #pragma unroll
        for (int ro = 0; ro < 2; ro++) {
            float tmax = -1e30f;
            #pragma unroll
            for (int nt = 0; nt < 8; nt++)
                tmax = fmaxf(tmax, fmaxf(s[nt][2 * ro], s[nt][2 * ro + 1]));
            tmax = fmaxf(tmax, __shfl_xor_sync(0xffffffffu, tmax, 1));
            tmax = fmaxf(tmax, __shfl_xor_sync(0xffffffffu, tmax, 2));
            float newm = fmaxf(mr[ro], tmax);
            float corr = __expf(mr[ro] - newm);
            mr[ro] = newm;
            float sum = 0.f;
            __half* Pw = ro ? Pw1 : Pw0;
            #pragma unroll
            for (int nt = 0; nt < 8; nt++) {
                float p0 = __expf(s[nt][2 * ro]     - newm);
                float p1 = __expf(s[nt][2 * ro + 1] - newm);
                sum += p0 + p1;
                *(__half2*)(Pw + nt * 8 + 2 * t) = __floats2half2_rn(p0, p1);
                O[nt][2 * ro]     *= corr;
                O[nt][2 * ro + 1] *= corr;
            }
            sum += __shfl_xor_sync(0xffffffffu, sum, 1);
            sum += __shfl_xor_sync(0xffffffffu, sum, 2);
            lr[ro] = lr[ro] * corr + sum;
        }
        __syncwarp();

        // O += P @ V   (V fragments via ldmatrix.trans)
        #pragma unroll
        for (int kc = 0; kc < 4; kc++) {           // key k-steps of 16
            uint32_t pa[4];
            pa[0] = ((const uint32_t*)Pw0)[kc * 8 + t];
            pa[1] = ((const uint32_t*)Pw1)[kc * 8 + t];
            pa[2] = ((const uint32_t*)Pw0)[kc * 8 + t + 4];
            pa[3] = ((const uint32_t*)Pw1)[kc * 8 + t + 4];
            #pragma unroll
            for (int nt = 0; nt < 8; nt++) {
                int lrow = kc * 16 + (lane & 15);
                uint32_t addr = smem_u32(Vs + lrow * ASTH + nt * 8);
                uint32_t b0, b1;
                ldmatrix_x2_trans(b0, b1, addr);
                uint32_t vb[2] = { b0, b1 };
                mma_f16(O[nt], pa, vb);
            }
        }
        __syncwarp();
    }

    // normalize + store ctx (half)
    float inv0 = 1.f / lr[0], inv1 = 1.f / lr[1];
    const int r0 = qt * 128 + wid * 16 + g;
    #pragma unroll
    for (int nt = 0; nt < 8; nt++) {
        int col = colbase + nt * 8 + 2 * t;
        *(__half2*)(ctx + ((size_t)r0 * B_ + b) * D_ + col) =
            __floats2half2_rn(O[nt][0] * inv0, O[nt][1] * inv0);
        *(__half2*)(ctx + ((size_t)(r0 + 8) * B_ + b) * D_ + col) =
            __floats2half2_rn(O[nt][2] * inv1, O[nt][3] * inv1);
    }
}

// ---------------- launch ------------------------------------------------------
extern "C" void kernel_launch(void* const* d_in, const int* in_sizes, int n_in,
                              void* d_out, int out_size) {
    const float* x     = (const float*)d_in[0];
    const float* ln1_g = (const float*)d_in[1];
    const float* ln1_b = (const float*)d_in[2];
    const float* ln2_g = (const float*)d_in[3];
    const float* ln2_b = (const float*)d_in[4];
    const float* Wq    = (const float*)d_in[5];
    const float* bq    = (const float*)d_in[6];
    const float* Wk    = (const float*)d_in[7];
    const float* bk    = (const float*)d_in[8];
    const float* Wv    = (const float*)d_in[9];
    const float* bv    = (const float*)d_in[10];
    const float* Wo    = (const float*)d_in[11];
    const float* bo    = (const float*)d_in[12];
    const float* W1    = (const float*)d_in[13];
    const float* b1    = (const float*)d_in[14];
    const float* W2    = (const float*)d_in[15];
    const float* b2    = (const float*)d_in[16];
    float* out = (float*)d_out;

    __half *ph, *pqkv, *pctx, *ph2, *pff, *wqkvT, *woT, *w1T, *w2T;
    float *px1, *bqkv;
    cudaGetSymbolAddress((void**)&ph,   g_h);
    cudaGetSymbolAddress((void**)&pqkv, g_qkv);
    cudaGetSymbolAddress((void**)&pctx, g_ctx);
    cudaGetSymbolAddress((void**)&px1,  g_x1);
    cudaGetSymbolAddress((void**)&ph2,  g_h2);
    cudaGetSymbolAddress((void**)&pff,  g_ff);
    cudaGetSymbolAddress((void**)&wqkvT,g_wqkvT);
    cudaGetSymbolAddress((void**)&bqkv, g_bqkv);
    cudaGetSymbolAddress((void**)&woT,  g_woT);
    cudaGetSymbolAddress((void**)&w1T,  g_w1T);
    cudaGetSymbolAddress((void**)&w2T,  g_w2T);

    cudaFuncSetAttribute(attn_mma, cudaFuncAttributeMaxDynamicSharedMemorySize, ATT_SMEM);
    cudaFuncSetAttribute((gemm_mma<1, __half>), cudaFuncAttributeMaxDynamicSharedMemorySize, GEMM_SMEM);
    cudaFuncSetAttribute((gemm_mma<2, float>),  cudaFuncAttributeMaxDynamicSharedMemorySize, GEMM_SMEM);
    cudaFuncSetAttribute((gemm_mma<3, __half>), cudaFuncAttributeMaxDynamicSharedMemorySize, GEMM_SMEM);

    // 0. transpose weights -> half [N,K]; Wq scaled by 1/sqrt(DH) (exact pow2)
    dim3 tb(32, 8);
    transpose_half<<<dim3(D_/32, D_/32), tb>>>(Wq, wqkvT,            D_, D_, 0.125f);
    transpose_half<<<dim3(D_/32, D_/32), tb>>>(Wk, wqkvT + 1024*D_,  D_, D_, 1.0f);
    transpose_half<<<dim3(D_/32, D_/32), tb>>>(Wv, wqkvT + 2048*D_,  D_, D_, 1.0f);
    transpose_half<<<dim3(D_/32, D_/32), tb>>>(Wo, woT, D_, D_, 1.0f);
    transpose_half<<<dim3(F_/32, D_/32), tb>>>(W1, w1T, D_, F_, 1.0f);
    transpose_half<<<dim3(D_/32, F_/32), tb>>>(W2, w2T, F_, D_, 1.0f);
    concat_bias<<<QKVS/256, 256>>>(bq, bk, bv, bqkv);

    // 1. h = half(LN1(x))
    ln_kernel<<<M_, 256>>>(x, ln1_g, ln1_b, ph);

    // 2. fused qkv = half(h @ [Wq*s|Wk|Wv] + [bq*s|bk|bv])
    gemm_mma<3, __half><<<dim3(QKVS / TN, M_ / TM), 256, GEMM_SMEM>>>(ph, wqkvT, bqkv, nullptr, pqkv, QKVS, D_);

    // 3. flash attention (fp16 mma) -> ctx (half)
    attn_mma<<<dim3(S_ / 128, B_ * H_), 256, ATT_SMEM>>>(pqkv, pctx);

    // 4. x1 = x + ctx @ Wo + bo   (float out)
    dim3 gD(D_ / TN, M_ / TM);
    gemm_mma<2, float><<<gD, 256, GEMM_SMEM>>>(pctx, woT, bo, x, px1, D_, D_);

    // 5. h2 = half(LN2(x1))
    ln_kernel<<<M_, 256>>>(px1, ln2_g, ln2_b, ph2);

    // 6. ff = half(relu(h2 @ W1 + b1))
    gemm_mma<1, __half><<<dim3(F_ / TN, M_ / TM), 256, GEMM_SMEM>>>(ph2, w1T, b1, nullptr, pff, F_, D_);

    // 7. out = x1 + ff @ W2 + b2   (float out)
    gemm_mma<2, float><<<gD, 256, GEMM_SMEM>>>(pff, w2T, b2, px1, out, D_, F_);
}

// round 15
// speedup vs baseline: 6.5190x; 1.0622x over previous
#include <cuda_runtime.h>
#include <cuda_fp16.h>
#include <cstdint>
#include <math.h>

#define S_  2048
#define B_  4
#define D_  1024
#define H_  16
#define DH_ 64
#define F_  4096
#define M_  8192   // S_*B_
#define QKVS 3072  // fused qkv row stride

// ---------------- scratch (device globals; no allocation allowed) ------------
__device__ __half g_h   [M_ * D_];
__device__ __half g_qkv [(size_t)M_ * QKVS];
__device__ __half g_ctx [M_ * D_];
__device__ float  g_x1  [M_ * D_];
__device__ __half g_h2  [M_ * D_];
__device__ __half g_ff  [(size_t)M_ * F_];
// transposed (half) weights, [N, K] K-major
__device__ __half g_wqkvT[(size_t)QKVS * D_];  // rows: 0-1023 Wq*0.125, 1024-2047 Wk, 2048-3071 Wv
__device__ float  g_bqkv [QKVS];
__device__ __half g_woT[D_ * D_];
__device__ __half g_w1T[(size_t)F_ * D_];   // [4096,1024]
__device__ __half g_w2T[(size_t)D_ * F_];   // [1024,4096]

// ---------------- helpers -----------------------------------------------------
__device__ __forceinline__ uint32_t smem_u32(const void* p) {
    uint32_t a;
    asm("{ .reg .u64 t; cvta.to.shared.u64 t, %1; cvt.u32.u64 %0, t; }" : "=r"(a) : "l"(p));
    return a;
}
#define CP_ASYNC16(dst, src) \
    asm volatile("cp.async.cg.shared.global [%0], [%1], 16;" :: "r"(dst), "l"(src))
#define CP_COMMIT() asm volatile("cp.async.commit_group;" ::: "memory")

__device__ __forceinline__ void mma_f16(float* c, const uint32_t* a, const uint32_t* b) {
    asm volatile(
        "mma.sync.aligned.m16n8k16.row.col.f32.f16.f16.f32 "
        "{%0,%1,%2,%3}, {%4,%5,%6,%7}, {%8,%9}, {%0,%1,%2,%3};"
        : "+f"(c[0]), "+f"(c[1]), "+f"(c[2]), "+f"(c[3])
        : "r"(a[0]), "r"(a[1]), "r"(a[2]), "r"(a[3]), "r"(b[0]), "r"(b[1]));
}
__device__ __forceinline__ void ldmatrix_x4(uint32_t* r, uint32_t addr) {
    asm volatile("ldmatrix.sync.aligned.m8n8.x4.shared.b16 {%0,%1,%2,%3}, [%4];"
                 : "=r"(r[0]), "=r"(r[1]), "=r"(r[2]), "=r"(r[3]) : "r"(addr));
}
__device__ __forceinline__ void ldmatrix_x2(uint32_t* r, uint32_t addr) {
    asm volatile("ldmatrix.sync.aligned.m8n8.x2.shared.b16 {%0,%1}, [%2];"
                 : "=r"(r[0]), "=r"(r[1]) : "r"(addr));
}
__device__ __forceinline__ void ldmatrix_x2_trans(uint32_t& r0, uint32_t& r1, uint32_t addr) {
    asm volatile("ldmatrix.sync.aligned.m8n8.x2.trans.shared.b16 {%0,%1}, [%2];"
                 : "=r"(r0), "=r"(r1) : "r"(addr));
}
__device__ __forceinline__ uint32_t h2_bits(__half2 h) {
    uint32_t u;
    *(__half2*)&u = h;
    return u;
}

// ---------------- fp16 mma.sync GEMM ------------------------------------------
// C[M,N] = A[M,K] @ Bt[N,K]^T (+epilogue). A,Bt half; accum fp32.
// 128x128 tile, 256 thr (8 warps 2x4, warp tile 64x32), K-chunk 64 halfs,
// 3-stage cp.async ring, ldmatrix fragments, 2 CTAs/SM.
#define TM    128
#define TN    128
#define TK    64
#define NSTG  3
#define LDH   72                       // smem row stride in halfs (144B: conflict-free)
#define TILEH (128 * LDH)
#define GEMM_SMEM (NSTG * 2 * TILEH * 2)   // 110592 bytes

// EPI: 1 half(relu(+bias)) | 2 +bias+residual (float out) | 3 half(+bias)
template<int EPI, typename OutT>
__global__ void __launch_bounds__(256, 2)
gemm_mma(const __half* __restrict__ A, const __half* __restrict__ Bt,
         const float* __restrict__ bias, const float* __restrict__ res,
         OutT* __restrict__ C, int N, int K) {
    extern __shared__ __half smh[];
    __half* As = smh;
    __half* Bs = smh + NSTG * TILEH;

    const int tid  = threadIdx.x;
    const int lane = tid & 31, wid = tid >> 5;
    const int wm = wid & 1, wn = wid >> 1;
    const int m0 = blockIdx.y * TM, n0 = blockIdx.x * TN;
    const int g = lane >> 2, t = lane & 3;
    const int CH = K / TK;

    float c[4][4][4];
    #pragma unroll
    for (int i = 0; i < 4; i++)
        #pragma unroll
        for (int j = 0; j < 4; j++)
            #pragma unroll
            for (int r = 0; r < 4; r++) c[i][j][r] = 0.f;

    // ldmatrix per-lane address components (within warp tile)
    const int a_row = (lane & 15);              // + i*16
    const int a_koff = (lane >> 4) * 8;         // + kc*16
    const int b_row = (lane & 7);               // + j*8
    const int b_koff = ((lane >> 3) & 1) * 8;   // + kc*16

    auto load_stage = [&](int cc, int s) {
        const __half* Ab = A  + (size_t)m0 * K + cc * TK;
        const __half* Bb = Bt + (size_t)n0 * K + cc * TK;
        __half* as = As + s * TILEH;
        __half* bs = Bs + s * TILEH;
        // 256 rows (A:128, B:128) x 8 granules of 16B = 2048 granules, 8/thread
        #pragma unroll
        for (int i = 0; i < 8; i++) {
            int gi = tid + 256 * i;            // 0..2047
            int mat = gi >> 10;                // 0:A 1:B
            int o = gi & 1023;
            int r = o >> 3, gc = o & 7;
            if (mat == 0)
                CP_ASYNC16(smem_u32(as + r * LDH + gc * 8), Ab + (size_t)r * K + gc * 8);
            else
                CP_ASYNC16(smem_u32(bs + r * LDH + gc * 8), Bb + (size_t)r * K + gc * 8);
        }
        CP_COMMIT();
    };

    load_stage(0, 0);
    load_stage(1, 1);

    for (int cc = 0; cc < CH; cc++) {
        if (cc == CH - 1) asm volatile("cp.async.wait_group 0;" ::: "memory");
        else              asm volatile("cp.async.wait_group 1;" ::: "memory");
        __syncthreads();

        if (cc + 2 < CH) load_stage(cc + 2, (cc + 2) % NSTG);

        const __half* as = As + (cc % NSTG) * TILEH + (wm * 64) * LDH;
        const __half* bs = Bs + (cc % NSTG) * TILEH + (wn * 32) * LDH;

        #pragma unroll
        for (int kc = 0; kc < 4; kc++) {           // 4 k-steps of 16 halfs
            uint32_t af[4][4], bf[4][2];
            #pragma unroll
            for (int i = 0; i < 4; i++)
                ldmatrix_x4(af[i], smem_u32(as + (i * 16 + a_row) * LDH + kc * 16 + a_koff));
            #pragma unroll
            for (int j = 0; j < 4; j++)
                ldmatrix_x2(bf[j], smem_u32(bs + (j * 8 + b_row) * LDH + kc * 16 + b_koff));
            #pragma unroll
            for (int i = 0; i < 4; i++)
                #pragma unroll
                for (int j = 0; j < 4; j++)
                    mma_f16(c[i][j], af[i], bf[j]);
        }
    }

    #pragma unroll
    for (int i = 0; i < 4; i++) {
        const int r0 = m0 + wm * 64 + i * 16 + g;
        #pragma unroll
        for (int j = 0; j < 4; j++) {
            const int col = n0 + wn * 32 + j * 8 + 2 * t;
            float b0 = bias[col], b1 = bias[col + 1];
            float v0 = c[i][j][0] + b0, v1 = c[i][j][1] + b1;
            float v2 = c[i][j][2] + b0, v3 = c[i][j][3] + b1;
            if (EPI == 1) {
                v0 = fmaxf(v0, 0.f); v1 = fmaxf(v1, 0.f);
                v2 = fmaxf(v2, 0.f); v3 = fmaxf(v3, 0.f);
            }
            if (EPI == 2) {
                float2 ra = *(const float2*)(res + (size_t)r0 * N + col);
                float2 rb = *(const float2*)(res + (size_t)(r0 + 8) * N + col);
                v0 += ra.x; v1 += ra.y; v2 += rb.x; v3 += rb.y;
                *(float2*)((float*)C + (size_t)r0 * N + col)       = make_float2(v0, v1);
                *(float2*)((float*)C + (size_t)(r0 + 8) * N + col) = make_float2(v2, v3);
            } else {
                *(__half2*)((__half*)C + (size_t)r0 * N + col) =
                    __floats2half2_rn(v0, v1);
                *(__half2*)((__half*)C + (size_t)(r0 + 8) * N + col) =
                    __floats2half2_rn(v2, v3);
            }
        }
    }
}

// ---------------- weight transpose -> half (+scale fold) ----------------------
__global__ void transpose_half(const float* __restrict__ in, __half* __restrict__ out,
                               int K, int N, float scale) {
    __shared__ float t[32][33];
    int n0 = blockIdx.x * 32, k0 = blockIdx.y * 32;
    #pragma unroll
    for (int i = threadIdx.y; i < 32; i += 8)
        t[i][threadIdx.x] = in[(size_t)(k0 + i) * N + n0 + threadIdx.x];
    __syncthreads();
    #pragma unroll
    for (int i = threadIdx.y; i < 32; i += 8)
        out[(size_t)(n0 + i) * K + k0 + threadIdx.x] = __float2half_rn(t[threadIdx.x][i] * scale);
}

__global__ void concat_bias(const float* __restrict__ bq, const float* __restrict__ bk,
                            const float* __restrict__ bv, float* __restrict__ out) {
    int i = blockIdx.x * 256 + threadIdx.x;
    float v = (i < 1024) ? bq[i] * 0.125f : (i < 2048) ? bk[i - 1024] : bv[i - 2048];
    out[i] = v;
}

// ---------------- block reduction --------------------------------------------
__device__ __forceinline__ float blockReduceSum256(float val) {
    __shared__ float sh[8];
    #pragma unroll
    for (int o = 16; o; o >>= 1) val += __shfl_xor_sync(0xffffffffu, val, o);
    int w = threadIdx.x >> 5;
    if ((threadIdx.x & 31) == 0) sh[w] = val;
    __syncthreads();
    float tot = 0.f;
    #pragma unroll
    for (int i = 0; i < 8; i++) tot += sh[i];
    __syncthreads();
    return tot;
}

// ---------------- LayerNorm: f32 in -> half out -------------------------------
__global__ void ln_kernel(const float* __restrict__ x,
                          const float* __restrict__ g,
                          const float* __restrict__ b,
                          __half* __restrict__ out) {
    int row = blockIdx.x;
    const float4* xr = (const float4*)(x + (size_t)row * D_);
    float4 xv = xr[threadIdx.x];

    float s = xv.x + xv.y + xv.z + xv.w;
    float mean = blockReduceSum256(s) * (1.0f / D_);

    float dx0 = xv.x - mean, dx1 = xv.y - mean, dx2 = xv.z - mean, dx3 = xv.w - mean;
    float s2 = dx0*dx0 + dx1*dx1 + dx2*dx2 + dx3*dx3;
    float var = blockReduceSum256(s2) * (1.0f / D_);
    float inv = rsqrtf(var + 1e-5f);

    float4 gv = ((const float4*)g)[threadIdx.x];
    float4 bv = ((const float4*)b)[threadIdx.x];
    __half2 h0 = __floats2half2_rn(dx0 * inv * gv.x + bv.x, dx1 * inv * gv.y + bv.y);
    __half2 h1 = __floats2half2_rn(dx2 * inv * gv.z + bv.z, dx3 * inv * gv.w + bv.w);
    uint2 pk = make_uint2(h2_bits(h0), h2_bits(h1));
    *(uint2*)(out + (size_t)row * D_ + 4 * threadIdx.x) = pk;
}

// ---------------- Flash attention, fp16 mma.sync -------------------------------
// grid (S/128, B*H), 256 thr (8 warps x 16 Q rows). q/k/v half, fused buffer.
#define ASTH 72                         // smem row stride (halfs)
#define NKT (S_ / 64)
#define ATT_SMEM (5 * 128 * ASTH * 2)   // 92160 bytes

__global__ void __launch_bounds__(256, 1)
attn_mma(const __half* __restrict__ qkv, __half* __restrict__ ctx) {
    extern __shared__ __half smh[];
    __half* Qs = smh;                    // [128][ASTH]
    __half* Ps = smh + 128 * ASTH;       // [128][ASTH]
    __half* KV = smh + 256 * ASTH;       // 3 x [128][ASTH]: rows 0-63 K, 64-127 V

    const int tid = threadIdx.x;
    const int lane = tid & 31, wid = tid >> 5;
    const int g = lane >> 2, t = lane & 3;
    const int bh = blockIdx.y, b = bh >> 4, h = bh & 15;
    const int qt = blockIdx.x;
    const int colbase = h * 64;
    const __half* q = qkv;
    const __half* k = qkv + 1024;
    const __half* v = qkv + 2048;

    auto issue_kv = [&](int kt) {
        __half* st = KV + (kt % 3) * 128 * ASTH;
        #pragma unroll
        for (int j = 0; j < 4; j++) {
            int gi = tid + 256 * j;          // 0..1023
            int r = (gi & 511) >> 3, c8 = (gi & 7) << 3;
            const __half* src = (gi < 512)
                ? k + ((size_t)(kt * 64 + r) * B_ + b) * QKVS + colbase + c8
                : v + ((size_t)(kt * 64 + r) * B_ + b) * QKVS + colbase + c8;
            __half* dst = st + ((gi < 512) ? r : (64 + r)) * ASTH + c8;
            CP_ASYNC16(smem_u32(dst), src);
        }
        CP_COMMIT();
    };
    issue_kv(0);
    issue_kv(1);

    // load Q tile
    for (int i = tid; i < 128 * 8; i += 256) {
        int r = i >> 3, c8 = (i & 7) << 3;
        *(uint4*)(Qs + r * ASTH + c8) =
            *(const uint4*)(q + ((size_t)(qt * 128 + r) * B_ + b) * QKVS + colbase + c8);
    }
    __syncthreads();

    // Q fragments: 4 k-steps of 16 (DH=64)
    uint32_t qf[4][4];
    {
        const uint32_t* q0 = (const uint32_t*)(Qs + (wid * 16 + g) * ASTH);
        const uint32_t* q1 = (const uint32_t*)(Qs + (wid * 16 + g + 8) * ASTH);
        #pragma unroll
        for (int kc = 0; kc < 4; kc++) {
            qf[kc][0] = q0[kc * 8 + t];
            qf[kc][1] = q1[kc * 8 + t];
            qf[kc][2] = q0[kc * 8 + t + 4];
            qf[kc][3] = q1[kc * 8 + t + 4];
        }
    }

    float mr[2] = {-1e30f, -1e30f}, lr[2] = {0.f, 0.f};
    float O[8][4];
    #pragma unroll
    for (int nt = 0; nt < 8; nt++)
        #pragma unroll
        for (int r = 0; r < 4; r++) O[nt][r] = 0.f;

    __half* Pw0 = Ps + (wid * 16 + g) * ASTH;
    __half* Pw1 = Ps + (wid * 16 + g + 8) * ASTH;

    for (int kt = 0; kt < NKT; kt++) {
        if (kt == NKT - 1) asm volatile("cp.async.wait_group 0;" ::: "memory");
        else               asm volatile("cp.async.wait_group 1;" ::: "memory");
        __syncthreads();
        if (kt + 2 < NKT) issue_kv(kt + 2);

        const __half* Ks = KV + (kt % 3) * 128 * ASTH;
        const __half* Vs = Ks + 64 * ASTH;

        // S = Q @ K^T
        float s[8][4];
        #pragma unroll
        for (int nt = 0; nt < 8; nt++)
            #pragma unroll
            for (int r = 0; r < 4; r++) s[nt][r] = 0.f;

        #pragma unroll
        for (int kc = 0; kc < 4; kc++) {
            #pragma unroll
            for (int nt = 0; nt < 8; nt++) {
                const uint32_t* kp = (const uint32_t*)(Ks + (nt * 8 + g) * ASTH) + kc * 8 + t;
                uint32_t bf[2] = { kp[0], kp[4] };
                mma_f16(s[nt], qf[kc], bf);
            }
        }

        // online softmax (rows g and g+8)
        #pragma unroll
        for (int ro = 0; ro < 2; ro++) {
            float tmax = -1e30f;
            #pragma unroll
            for (int nt = 0; nt < 8; nt++)
                tmax = fmaxf(tmax, fmaxf(s[nt][2 * ro], s[nt][2 * ro + 1]));
            tmax = fmaxf(tmax, __shfl_xor_sync(0xffffffffu, tmax, 1));
            tmax = fmaxf(tmax, __shfl_xor_sync(0xffffffffu, tmax, 2));
            float newm = fmaxf(mr[ro], tmax);
            float corr = __expf(mr[ro] - newm);
            mr[ro] = newm;
            float sum = 0.f;
            __half* Pw = ro ? Pw1 : Pw0;
            #pragma unroll
            for (int nt = 0; nt < 8; nt++) {
                float p0 = __expf(s[nt][2 * ro]     - newm);
                float p1 = __expf(s[nt][2 * ro + 1] - newm);
                sum += p0 + p1;
                *(__half2*)(Pw + nt * 8 + 2 * t) = __floats2half2_rn(p0, p1);
                O[nt][2 * ro]     *= corr;
                O[nt][2 * ro + 1] *= corr;
            }
            sum += __shfl_xor_sync(0xffffffffu, sum, 1);
            sum += __shfl_xor_sync(0xffffffffu, sum, 2);
            lr[ro] = lr[ro] * corr + sum;
        }
        __syncwarp();

        // O += P @ V   (V fragments via ldmatrix.trans)
        #pragma unroll
        for (int kc = 0; kc < 4; kc++) {           // key k-steps of 16
            uint32_t pa[4];
            pa[0] = ((const uint32_t*)Pw0)[kc * 8 + t];
            pa[1] = ((const uint32_t*)Pw1)[kc * 8 + t];
            pa[2] = ((const uint32_t*)Pw0)[kc * 8 + t + 4];
            pa[3] = ((const uint32_t*)Pw1)[kc * 8 + t + 4];
            #pragma unroll
            for (int nt = 0; nt < 8; nt++) {
                int lrow = kc * 16 + (lane & 15);
                uint32_t addr = smem_u32(Vs + lrow * ASTH + nt * 8);
                uint32_t b0, b1;
                ldmatrix_x2_trans(b0, b1, addr);
                uint32_t vb[2] = { b0, b1 };
                mma_f16(O[nt], pa, vb);
            }
        }
        __syncwarp();
    }

    // normalize + store ctx (half)
    float inv0 = 1.f / lr[0], inv1 = 1.f / lr[1];
    const int r0 = qt * 128 + wid * 16 + g;
    #pragma unroll
    for (int nt = 0; nt < 8; nt++) {
        int col = colbase + nt * 8 + 2 * t;
        *(__half2*)(ctx + ((size_t)r0 * B_ + b) * D_ + col) =
            __floats2half2_rn(O[nt][0] * inv0, O[nt][1] * inv0);
        *(__half2*)(ctx + ((size_t)(r0 + 8) * B_ + b) * D_ + col) =
            __floats2half2_rn(O[nt][2] * inv1, O[nt][3] * inv1);
    }
}

// ---------------- launch ------------------------------------------------------
extern "C" void kernel_launch(void* const* d_in, const int* in_sizes, int n_in,
                              void* d_out, int out_size) {
    const float* x     = (const float*)d_in[0];
    const float* ln1_g = (const float*)d_in[1];
    const float* ln1_b = (const float*)d_in[2];
    const float* ln2_g = (const float*)d_in[3];
    const float* ln2_b = (const float*)d_in[4];
    const float* Wq    = (const float*)d_in[5];
    const float* bq    = (const float*)d_in[6];
    const float* Wk    = (const float*)d_in[7];
    const float* bk    = (const float*)d_in[8];
    const float* Wv    = (const float*)d_in[9];
    const float* bv    = (const float*)d_in[10];
    const float* Wo    = (const float*)d_in[11];
    const float* bo    = (const float*)d_in[12];
    const float* W1    = (const float*)d_in[13];
    const float* b1    = (const float*)d_in[14];
    const float* W2    = (const float*)d_in[15];
    const float* b2    = (const float*)d_in[16];
    float* out = (float*)d_out;

    __half *ph, *pqkv, *pctx, *ph2, *pff, *wqkvT, *woT, *w1T, *w2T;
    float *px1, *bqkv;
    cudaGetSymbolAddress((void**)&ph,   g_h);
    cudaGetSymbolAddress((void**)&pqkv, g_qkv);
    cudaGetSymbolAddress((void**)&pctx, g_ctx);
    cudaGetSymbolAddress((void**)&px1,  g_x1);
    cudaGetSymbolAddress((void**)&ph2,  g_h2);
    cudaGetSymbolAddress((void**)&pff,  g_ff);
    cudaGetSymbolAddress((void**)&wqkvT,g_wqkvT);
    cudaGetSymbolAddress((void**)&bqkv, g_bqkv);
    cudaGetSymbolAddress((void**)&woT,  g_woT);
    cudaGetSymbolAddress((void**)&w1T,  g_w1T);
    cudaGetSymbolAddress((void**)&w2T,  g_w2T);

    cudaFuncSetAttribute(attn_mma, cudaFuncAttributeMaxDynamicSharedMemorySize, ATT_SMEM);
    cudaFuncSetAttribute((gemm_mma<1, __half>), cudaFuncAttributeMaxDynamicSharedMemorySize, GEMM_SMEM);
    cudaFuncSetAttribute((gemm_mma<2, float>),  cudaFuncAttributeMaxDynamicSharedMemorySize, GEMM_SMEM);
    cudaFuncSetAttribute((gemm_mma<3, __half>), cudaFuncAttributeMaxDynamicSharedMemorySize, GEMM_SMEM);

    // 0. transpose weights -> half [N,K]; Wq scaled by 1/sqrt(DH) (exact pow2)
    dim3 tb(32, 8);
    transpose_half<<<dim3(D_/32, D_/32), tb>>>(Wq, wqkvT,            D_, D_, 0.125f);
    transpose_half<<<dim3(D_/32, D_/32), tb>>>(Wk, wqkvT + 1024*D_,  D_, D_, 1.0f);
    transpose_half<<<dim3(D_/32, D_/32), tb>>>(Wv, wqkvT + 2048*D_,  D_, D_, 1.0f);
    transpose_half<<<dim3(D_/32, D_/32), tb>>>(Wo, woT, D_, D_, 1.0f);
    transpose_half<<<dim3(F_/32, D_/32), tb>>>(W1, w1T, D_, F_, 1.0f);
    transpose_half<<<dim3(D_/32, F_/32), tb>>>(W2, w2T, F_, D_, 1.0f);
    concat_bias<<<QKVS/256, 256>>>(bq, bk, bv, bqkv);

    // 1. h = half(LN1(x))
    ln_kernel<<<M_, 256>>>(x, ln1_g, ln1_b, ph);

    // 2. fused qkv = half(h @ [Wq*s|Wk|Wv] + [bq*s|bk|bv])
    gemm_mma<3, __half><<<dim3(QKVS / TN, M_ / TM), 256, GEMM_SMEM>>>(ph, wqkvT, bqkv, nullptr, pqkv, QKVS, D_);

    // 3. flash attention (fp16 mma) -> ctx (half)
    attn_mma<<<dim3(S_ / 128, B_ * H_), 256, ATT_SMEM>>>(pqkv, pctx);

    // 4. x1 = x + ctx @ Wo + bo   (float out)
    dim3 gD(D_ / TN, M_ / TM);
    gemm_mma<2, float><<<gD, 256, GEMM_SMEM>>>(pctx, woT, bo, x, px1, D_, D_);

    // 5. h2 = half(LN2(x1))
    ln_kernel<<<M_, 256>>>(px1, ln2_g, ln2_b, ph2);

    // 6. ff = half(relu(h2 @ W1 + b1))
    gemm_mma<1, __half><<<dim3(F_ / TN, M_ / TM), 256, GEMM_SMEM>>>(ph2, w1T, b1, nullptr, pff, F_, D_);

    // 7. out = x1 + ff @ W2 + b2   (float out)
    gemm_mma<2, float><<<gD, 256, GEMM_SMEM>>>(pff, w2T, b2, px1, out, D_, F_);
}